// round 15
// baseline (speedup 1.0000x reference)
#include <cuda_runtime.h>
#include <cuda_bf16.h>
#include <math.h>
#include <stdint.h>

#define NN 50000
#define EE 800000
#define BB 64
#define HH 128
#define TILES64 782   // ceil(50000/64)
#define SPLITS 8

// ---------------- scratch (device globals) ----------------
// x as interleaved bf16 hi/lo: per node 128 uint32 = [64 hi words | 64 lo words]
__device__ uint32_t g_xA [NN * 128];
__device__ uint32_t g_xB [NN * 128];
__device__ uint32_t g_agg[NN * 64];   // single bf16 plane (hi only)
__device__ float g_v   [NN * HH];
__device__ float g_scores[NN * 4];
__device__ float g_U[HH * 4];
__device__ float g_cvec[4];
__device__ float g_pm[BB * SPLITS * 4];
__device__ float g_pd[BB * SPLITS * 4];
__device__ float g_pp[BB * SPLITS * 128];
__device__ int   g_deg[NN];
__device__ int   g_off[NN + 1];
__device__ int   g_cur[NN];
__device__ int   g_col[EE];
__device__ int   g_gstart[BB + 1];
__device__ uint4 g_wbuf[8 * 4096];

// ---------------- helpers ----------------
__device__ __forceinline__ void hilo(float v, uint32_t& h, uint32_t& l) {
    __nv_bfloat16 hb = __float2bfloat16(v);
    __nv_bfloat16 lb = __float2bfloat16(v - __bfloat162float(hb));
    h = (uint32_t)__bfloat16_as_ushort(hb);
    l = (uint32_t)__bfloat16_as_ushort(lb);
}
__device__ __forceinline__ uint32_t bfh(float v) {
    return (uint32_t)__bfloat16_as_ushort(__float2bfloat16(v));
}
__device__ __forceinline__ float2 bf2f(uint32_t u) {
    __nv_bfloat162 h;
    *reinterpret_cast<uint32_t*>(&h) = u;
    return __bfloat1622float2(h);
}
__device__ __forceinline__ uint32_t smem_u32(const void* p) {
    uint32_t a;
    asm("{ .reg .u64 t; cvta.to.shared.u64 t, %1; cvt.u32.u64 %0, t; }" : "=r"(a) : "l"(p));
    return a;
}
__device__ __forceinline__ float warp_sum(float v) {
#pragma unroll
    for (int o = 16; o > 0; o >>= 1) v += __shfl_xor_sync(0xffffffffu, v, o);
    return v;
}

#define HMMA(C, A0, A1, A2, A3, B0, B1) \
    asm volatile("mma.sync.aligned.m16n8k16.row.col.f32.bf16.bf16.f32 " \
                 "{%0,%1,%2,%3}, {%4,%5,%6,%7}, {%8,%9}, {%0,%1,%2,%3};" \
                 : "+f"((C)[0]), "+f"((C)[1]), "+f"((C)[2]), "+f"((C)[3]) \
                 : "r"(A0), "r"(A1), "r"(A2), "r"(A3), "r"(B0), "r"(B1))

#define LDSM4(D0, D1, D2, D3, A) \
    asm volatile("ldmatrix.sync.aligned.m8n8.x4.shared.b16 {%0,%1,%2,%3}, [%4];" \
                 : "=r"(D0), "=r"(D1), "=r"(D2), "=r"(D3) : "r"(A))

#define CP_ASYNC16(dst, src, sz) \
    asm volatile("cp.async.cg.shared.global [%0], [%1], 16, %2;" \
                 :: "r"(dst), "l"(src), "r"(sz) : "memory")
#define CP_COMMIT() asm volatile("cp.async.commit_group;" ::: "memory")
#define CP_WAIT0()  asm volatile("cp.async.wait_group 0;" ::: "memory")

// ---------------- SMEM layout (64-row tile) ----------------
#define OFF_AH  0
#define OFF_AL  16384
#define OFF_WH  32768
#define OFF_WL  65536
#define OFF_MISC 98304
#define OFF_BIAS (OFF_MISC)
#define OFF_G    (OFF_MISC + 512)
#define OFF_BETA (OFF_MISC + 1024)
#define OFF_MEAN (OFF_MISC + 1536)
#define OFF_RSTD (OFF_MISC + 1856)
#define OFF_U    (OFF_MISC + 2176)
#define OFF_CV   (OFF_MISC + 4224)
#define SMEM_BYTES (OFF_MISC + 4256)

__device__ __forceinline__ int CIDX(int row, int col) {
    return row * 128 + (((col >> 2) ^ (row & 7)) << 2) + (col & 3);
}
__device__ __forceinline__ int PIDX(int row, int cp) {
    return row * 64 + (((cp >> 2) ^ (row & 7)) << 2) + (cp & 3);
}

// ---------------- setup1: CSR init + weight pre-conversion ----------------
__global__ void k_setup1(const float* w0, const float* w1, const float* w2, const float* w3,
                         const float* w4, const float* w5, const float* w6, const float* w7) {
    int b = blockIdx.x;
    if (b < 196) {
        int i = b * 256 + threadIdx.x;
        if (i < NN) { g_deg[i] = 0; g_cur[i] = 0; }
        return;
    }
    int bb = b - 196;
    int m = bb >> 4;
    const float* W;
    switch (m) {
        case 0: W = w0; break; case 1: W = w1; break; case 2: W = w2; break;
        case 3: W = w3; break; case 4: W = w4; break; case 5: W = w5; break;
        case 6: W = w6; break; default: W = w7; break;
    }
    int i = (bb & 15) * 256 + threadIdx.x;
    int row = i >> 5, q = i & 31;
    float4 v = *reinterpret_cast<const float4*>(W + (size_t)row * 128 + q * 4);
    uint32_t h0, l0, h1, l1, h2, l2, h3, l3;
    hilo(v.x, h0, l0); hilo(v.y, h1, l1); hilo(v.z, h2, l2); hilo(v.w, h3, l3);
    uint2 uh, ul;
    uh.x = h0 | (h1 << 16); uh.y = h2 | (h3 << 16);
    ul.x = l0 | (l1 << 16); ul.y = l2 | (l3 << 16);
    char* base = (char*)g_wbuf + (size_t)m * 65536;
    int sw = row * 256 + q * 8;
    *reinterpret_cast<uint2*>(base + sw)         = uh;
    *reinterpret_cast<uint2*>(base + 32768 + sw) = ul;
}

// ---------------- deg count (4 edges/thread, MLP=4) ----------------
__global__ void __launch_bounds__(256) k_deg(const int* __restrict__ ei) {
    int base = blockIdx.x * 1024 + threadIdx.x;
    int d0 = -1, d1 = -1, d2 = -1, d3 = -1;
    if (base < EE)        d0 = __ldg(&ei[EE + base]);
    if (base + 256 < EE)  d1 = __ldg(&ei[EE + base + 256]);
    if (base + 512 < EE)  d2 = __ldg(&ei[EE + base + 512]);
    if (base + 768 < EE)  d3 = __ldg(&ei[EE + base + 768]);
    if (d0 >= 0) atomicAdd(&g_deg[d0], 1);
    if (d1 >= 0) atomicAdd(&g_deg[d1], 1);
    if (d2 >= 0) atomicAdd(&g_deg[d2], 1);
    if (d3 >= 0) atomicAdd(&g_deg[d3], 1);
}

// ---------------- setup2: scan + attention prep + graph bounds ----------------
__global__ void __launch_bounds__(1024) k_setup2(const float* __restrict__ in_proj_W,
                                                 const float* __restrict__ in_proj_b,
                                                 const float* __restrict__ query,
                                                 const int* __restrict__ batch) {
    int t = threadIdx.x;
    if (blockIdx.x == 0) {
        __shared__ int sm[1024];
        const int chunk = (NN + 1023) / 1024;
        int base = t * chunk;
        int s = 0;
        for (int i = 0; i < chunk; ++i) {
            int idx = base + i;
            if (idx < NN) s += g_deg[idx];
        }
        sm[t] = s;
        __syncthreads();
        for (int d = 1; d < 1024; d <<= 1) {
            int add = (t >= d) ? sm[t - d] : 0;
            __syncthreads();
            sm[t] += add;
            __syncthreads();
        }
        int run = sm[t] - s;
        for (int i = 0; i < chunk; ++i) {
            int idx = base + i;
            if (idx < NN) { g_off[idx] = run; run += g_deg[idx]; }
        }
        if (t == 1023) g_off[NN] = sm[1023];
    } else if (blockIdx.x == 1) {
        __shared__ float qv[128];
        if (t < 128) {
            float s = in_proj_b[t];
            for (int k = 0; k < 128; ++k) s = fmaf(in_proj_W[t * 128 + k], query[k], s);
            qv[t] = s;
        }
        __syncthreads();
        if (t < 128) {
            const float inv = 1.0f / sqrtf(32.0f);
            float u[4] = {0.f, 0.f, 0.f, 0.f};
            for (int r = 0; r < 128; ++r) {
                float w = in_proj_W[(128 + r) * 128 + t];
                u[r >> 5] = fmaf(qv[r], w, u[r >> 5]);
            }
#pragma unroll
            for (int h = 0; h < 4; ++h) g_U[t * 4 + h] = u[h] * inv;
            if (t < 4) {
                float cc = 0.f;
                for (int d = 0; d < 32; ++d)
                    cc = fmaf(qv[t * 32 + d], in_proj_b[128 + t * 32 + d], cc);
                g_cvec[t] = cc * inv;
            }
        }
    } else {
        int i = (blockIdx.x - 2) * 1024 + t;
        if (i >= NN) return;
        int bi = batch[i];
        if (i == 0) {
            for (int g = 0; g <= bi; ++g) g_gstart[g] = 0;
        } else {
            int bp = batch[i - 1];
            for (int g = bp + 1; g <= bi; ++g) g_gstart[g] = i;
        }
        if (i == NN - 1) {
            for (int g = bi + 1; g <= BB; ++g) g_gstart[g] = NN;
        }
    }
}

// ---------------- CSR fill (4 edges/thread, MLP=4) ----------------
__global__ void __launch_bounds__(256) k_fill(const int* __restrict__ ei) {
    int base = blockIdx.x * 1024 + threadIdx.x;
    int s0 = 0, s1 = 0, s2 = 0, s3 = 0;
    int d0 = -1, d1 = -1, d2 = -1, d3 = -1;
    if (base < EE)       { s0 = __ldg(&ei[base]);       d0 = __ldg(&ei[EE + base]); }
    if (base + 256 < EE) { s1 = __ldg(&ei[base + 256]); d1 = __ldg(&ei[EE + base + 256]); }
    if (base + 512 < EE) { s2 = __ldg(&ei[base + 512]); d2 = __ldg(&ei[EE + base + 512]); }
    if (base + 768 < EE) { s3 = __ldg(&ei[base + 768]); d3 = __ldg(&ei[EE + base + 768]); }
    if (d0 >= 0) { int sl = atomicAdd(&g_cur[d0], 1); g_col[g_off[d0] + sl] = s0; }
    if (d1 >= 0) { int sl = atomicAdd(&g_cur[d1], 1); g_col[g_off[d1] + sl] = s1; }
    if (d2 >= 0) { int sl = atomicAdd(&g_cur[d2], 1); g_col[g_off[d2] + sl] = s2; }
    if (d3 >= 0) { int sl = atomicAdd(&g_cur[d3], 1); g_col[g_off[d3] + sl] = s3; }
}

// ---------------- GEMM fills ----------------
__device__ __forceinline__ void fill_copy_async(const uint32_t* __restrict__ g,
                                                uint32_t sb, int tile0, int nrows, int t) {
#pragma unroll
    for (int rep = 0; rep < 4; ++rep) {
        int i = t + rep * 512;
        int row = i >> 5, c = i & 31;
        int grow = tile0 + row;
        int sz = (grow < nrows) ? 16 : 0;
        const char* src = (const char*)(g + (size_t)grow * 128) + c * 16;
        int cc = c & 15;
        int phys = row * 256 + ((cc ^ (row & 7)) << 4);
        uint32_t dst = sb + ((c < 16) ? OFF_AH : OFF_AL) + phys;
        CP_ASYNC16(dst, src, sz);
    }
}
__device__ __forceinline__ void fill_W_async(int slot, uint32_t sb, int t) {
    const char* src = (const char*)g_wbuf + (size_t)slot * 65536;
#pragma unroll
    for (int rep = 0; rep < 4; ++rep) {
        int i = t + rep * 512;
        int row = i >> 4, chunk = i & 15;
        int phys = row * 256 + ((chunk ^ (row & 7)) << 4);
        CP_ASYNC16(sb + OFF_WH + phys, src + i * 16, 16);
        CP_ASYNC16(sb + OFF_WL + phys, src + 32768 + i * 16, 16);
    }
}
__device__ __forceinline__ void fill_Whi_async(int slot, uint32_t sb, uint32_t dstoff, int t) {
    const char* src = (const char*)g_wbuf + (size_t)slot * 65536;
#pragma unroll
    for (int rep = 0; rep < 4; ++rep) {
        int i = t + rep * 512;
        int row = i >> 4, chunk = i & 15;
        int phys = row * 256 + ((chunk ^ (row & 7)) << 4);
        CP_ASYNC16(sb + dstoff + phys, src + i * 16, 16);
    }
}
__device__ __forceinline__ void fill_convert(const float* __restrict__ A, char* smem,
                                             int tile0, int nrows, int t) {
    float4 v[4];
#pragma unroll
    for (int rep = 0; rep < 4; ++rep) {
        int i = t + rep * 512;
        int row = i >> 5, q = i & 31;
        int grow = tile0 + row;
        v[rep] = make_float4(0.f, 0.f, 0.f, 0.f);
        if (grow < nrows)
            v[rep] = __ldg(reinterpret_cast<const float4*>(A + (size_t)grow * HH + q * 4));
    }
#pragma unroll
    for (int rep = 0; rep < 4; ++rep) {
        int i = t + rep * 512;
        int row = i >> 5, q = i & 31;
        uint32_t h0, l0, h1, l1, h2, l2, h3, l3;
        hilo(v[rep].x, h0, l0); hilo(v[rep].y, h1, l1);
        hilo(v[rep].z, h2, l2); hilo(v[rep].w, h3, l3);
        uint2 uh, ul;
        uh.x = h0 | (h1 << 16); uh.y = h2 | (h3 << 16);
        ul.x = l0 | (l1 << 16); ul.y = l2 | (l3 << 16);
        int phys = row * 256 + (((q >> 1) ^ (row & 7)) << 4) + (q & 1) * 8;
        *reinterpret_cast<uint2*>(smem + OFF_AH + phys) = uh;
        *reinterpret_cast<uint2*>(smem + OFF_AL + phys) = ul;
    }
}

// ---------------- generic mainloop (MODE 0/2) ----------------
// TERMS: 2 = Ah*Bh + Al*Bh | 3 = Ah*Bh + Ah*Bl + Al*Bh (B lo at boff+32768)
template <int TERMS>
__device__ __forceinline__ void mainloop(uint32_t sb, uint32_t aoff_hi, uint32_t aoff_lo,
                                         uint32_t boff, float c[4][4],
                                         int wm, int wn, int lane) {
    uint32_t rowA = wm * 16 + (lane & 15);
    uint32_t swA = rowA & 7;
    uint32_t aAddrH = sb + aoff_hi + rowA * 256;
    uint32_t aAddrL = sb + aoff_lo + rowA * 256;
    uint32_t halfA = lane >> 4;
    uint32_t wrow = sb + boff + (uint32_t)(wn * 32 + lane) * 256;
    uint32_t swB = lane & 7;
#pragma unroll
    for (int ks = 0; ks < 8; ++ks) {
        uint32_t bh0[4], bh1[4];
        uint32_t cb0 = (uint32_t)(((2 * ks) ^ swB) << 4);
        uint32_t cb1 = (uint32_t)(((2 * ks + 1) ^ swB) << 4);
        LDSM4(bh0[0], bh0[1], bh0[2], bh0[3], wrow + cb0);
        LDSM4(bh1[0], bh1[1], bh1[2], bh1[3], wrow + cb1);
        uint32_t bl0[4], bl1[4];
        if (TERMS == 3) {
            LDSM4(bl0[0], bl0[1], bl0[2], bl0[3], wrow + 32768 + cb0);
            LDSM4(bl1[0], bl1[1], bl1[2], bl1[3], wrow + 32768 + cb1);
        }
        uint32_t ca = (uint32_t)(((2 * ks + halfA) ^ swA) << 4);
        uint32_t ah0, ah1, ah2, ah3;
        LDSM4(ah0, ah1, ah2, ah3, aAddrH + ca);
        uint32_t al0, al1, al2, al3;
        LDSM4(al0, al1, al2, al3, aAddrL + ca);
#pragma unroll
        for (int nb = 0; nb < 4; ++nb) {
            HMMA(c[nb], ah0, ah1, ah2, ah3, bh0[nb], bh1[nb]);
            if (TERMS == 3) HMMA(c[nb], ah0, ah1, ah2, ah3, bl0[nb], bl1[nb]);
            HMMA(c[nb], al0, al1, al2, al3, bh0[nb], bh1[nb]);
        }
    }
}

// ---------------- fused SAGE mainloop (MODE 1) ----------------
// c += agg@Wl_hi (agg A-frags via direct LDG.32 from global)
//    + x_hi@Wr_hi + x_lo@Wr_hi (x planes via LDSM from SMEM)
__device__ __forceinline__ void mainloop_sage(uint32_t sb, const uint32_t* __restrict__ agg,
                                              int tile0, int nrows, float c[4][4],
                                              int wm, int wn, int lane) {
    uint32_t rowA = wm * 16 + (lane & 15);
    uint32_t swA = rowA & 7;
    uint32_t aAddrH = sb + OFF_AH + rowA * 256;
    uint32_t aAddrL = sb + OFF_AL + rowA * 256;
    uint32_t halfA = lane >> 4;
    uint32_t wlrow = sb + OFF_WH + (uint32_t)(wn * 32 + lane) * 256;
    uint32_t wrrow = sb + OFF_WL + (uint32_t)(wn * 32 + lane) * 256;
    uint32_t swB = lane & 7;
    // agg fragment pointers: a0/a2 row = wm*16+g, a1/a3 row = +8 (m16n8k16 A layout)
    int g = lane >> 2, tt = lane & 3;
    int r0 = tile0 + wm * 16 + g;
    int r1 = r0 + 8;
    bool v0 = (r0 < nrows), v1 = (r1 < nrows);
    const uint32_t* p0 = agg + (size_t)r0 * 64 + tt;
    const uint32_t* p1 = agg + (size_t)r1 * 64 + tt;
#pragma unroll
    for (int ks = 0; ks < 8; ++ks) {
        int kw = ks * 8;  // word offset for this k-step (16 bf16 = 8 words)
        uint32_t a0 = v0 ? __ldg(p0 + kw)     : 0u;
        uint32_t a1 = v1 ? __ldg(p1 + kw)     : 0u;
        uint32_t a2 = v0 ? __ldg(p0 + kw + 4) : 0u;
        uint32_t a3 = v1 ? __ldg(p1 + kw + 4) : 0u;
        uint32_t cb0 = (uint32_t)(((2 * ks) ^ swB) << 4);
        uint32_t cb1 = (uint32_t)(((2 * ks + 1) ^ swB) << 4);
        uint32_t wl0[4], wl1[4], wr0[4], wr1[4];
        LDSM4(wl0[0], wl0[1], wl0[2], wl0[3], wlrow + cb0);
        LDSM4(wl1[0], wl1[1], wl1[2], wl1[3], wlrow + cb1);
        LDSM4(wr0[0], wr0[1], wr0[2], wr0[3], wrrow + cb0);
        LDSM4(wr1[0], wr1[1], wr1[2], wr1[3], wrrow + cb1);
        uint32_t ca = (uint32_t)(((2 * ks + halfA) ^ swA) << 4);
        uint32_t xh0, xh1, xh2, xh3;
        LDSM4(xh0, xh1, xh2, xh3, aAddrH + ca);
        uint32_t xl0, xl1, xl2, xl3;
        LDSM4(xl0, xl1, xl2, xl3, aAddrL + ca);
#pragma unroll
        for (int nb = 0; nb < 4; ++nb) {
            HMMA(c[nb], a0, a1, a2, a3, wl0[nb], wl1[nb]);
            HMMA(c[nb], xh0, xh1, xh2, xh3, wr0[nb], wr1[nb]);
            HMMA(c[nb], xl0, xl1, xl2, xl3, wr0[nb], wr1[nb]);
        }
    }
}

// MODE: 0 = input proj (3-term, W hi/lo)
//       1 = SAGE fused: {Wl_hi->WH, Wr_hi->WL, x hi/lo->AH/AL}; agg via direct LDG;
//                       single mainloop; LN+relu+residual
//       2 = V proj + scores (2-term, Wv hi only)
template <int MODE>
__global__ void __launch_bounds__(512, 2) k_mma(
    const float* __restrict__ Afp,
    const uint32_t* __restrict__ p1, const uint32_t* __restrict__ p2,
    int wslot, const float* __restrict__ bias,
    const float* __restrict__ lng, const float* __restrict__ lnb,
    uint32_t* __restrict__ out, float* __restrict__ outf, int nrows)
{
    extern __shared__ char smem[];
    uint32_t sb = smem_u32(smem);
    int t = threadIdx.x, wid = t >> 5, lane = t & 31;
    int tile0 = blockIdx.x * 64;
    int wm = wid & 3, wn = wid >> 2;

    if (MODE == 0) {
        fill_W_async(wslot, sb, t);
    } else if (MODE == 1) {
        fill_Whi_async(wslot, sb, OFF_WH, t);       // Wl hi
        fill_Whi_async(wslot + 1, sb, OFF_WL, t);   // Wr hi
        fill_copy_async(p2, sb, tile0, nrows, t);   // x hi->AH, lo->AL
    } else {
        fill_Whi_async(wslot, sb, OFF_WH, t);
        fill_copy_async(p1, sb, tile0, nrows, t);
    }
    CP_COMMIT();

    if (t < 128) {
        ((float*)(smem + OFF_BIAS))[t] = bias[t];
        if (MODE == 1) {
            ((float*)(smem + OFF_G))[t]    = lng[t];
            ((float*)(smem + OFF_BETA))[t] = lnb[t];
        }
    }
    if (MODE == 2) {
        if (t >= 128 && t < 256) ((float4*)(smem + OFF_U))[t - 128] = ((const float4*)g_U)[t - 128];
        if (t == 256) *((float4*)(smem + OFF_CV)) = *((const float4*)g_cvec);
    }
    if (MODE == 0) fill_convert(Afp, smem, tile0, nrows, t);

    float c[4][4];
#pragma unroll
    for (int nb = 0; nb < 4; ++nb)
#pragma unroll
        for (int j = 0; j < 4; ++j) c[nb][j] = 0.f;

    CP_WAIT0();
    __syncthreads();

    if (MODE == 0)      mainloop<3>(sb, OFF_AH, OFF_AL, OFF_WH, c, wm, wn, lane);
    else if (MODE == 1) mainloop_sage(sb, p1, tile0, nrows, c, wm, wn, lane);
    else                mainloop<2>(sb, OFF_AH, OFF_AL, OFF_WH, c, wm, wn, lane);

    __syncthreads();

    if (MODE == 2) {
        if (t < 64) {
            int grow = tile0 + t;
            if (grow < nrows) {
                const uint32_t* ph = (const uint32_t*)(smem + OFF_AH);
                const uint32_t* pl = (const uint32_t*)(smem + OFF_AL);
                const float4* U4 = (const float4*)(smem + OFF_U);
                const float* cv = (const float*)(smem + OFF_CV);
                float a0 = cv[0], a1 = cv[1], a2 = cv[2], a3 = cv[3];
#pragma unroll
                for (int kk = 0; kk < 64; ++kk) {
                    int idx = PIDX(t, kk);
                    float2 h = bf2f(ph[idx]);
                    float2 l = bf2f(pl[idx]);
                    float x0 = h.x + l.x, x1 = h.y + l.y;
                    float4 u0 = U4[2 * kk];
                    float4 u1 = U4[2 * kk + 1];
                    a0 += x0 * u0.x + x1 * u1.x;
                    a1 += x0 * u0.y + x1 * u1.y;
                    a2 += x0 * u0.z + x1 * u1.z;
                    a3 += x0 * u0.w + x1 * u1.w;
                }
                float4 r; r.x = a0; r.y = a1; r.z = a2; r.w = a3;
                reinterpret_cast<float4*>(g_scores)[grow] = r;
            }
        }
        __syncthreads();
    }

    // spill C over W-hi region (dead after mainloops)
    float* Csm = (float*)(smem + OFF_WH);
    int g = lane >> 2, tt = lane & 3;
    {
        int r0 = wm * 16 + g;
        int r1 = r0 + 8;
#pragma unroll
        for (int nb = 0; nb < 4; ++nb) {
            int col = wn * 32 + nb * 8 + tt * 2;
            Csm[CIDX(r0, col)]     = c[nb][0];
            Csm[CIDX(r0, col + 1)] = c[nb][1];
            Csm[CIDX(r1, col)]     = c[nb][2];
            Csm[CIDX(r1, col + 1)] = c[nb][3];
        }
    }
    __syncthreads();

    const float* bs = (const float*)(smem + OFF_BIAS);
    if (MODE == 1) {
        if (t < 64) {
            float sum = 0.f, sq = 0.f;
#pragma unroll
            for (int j = 0; j < 128; ++j) {
                float x = Csm[CIDX(t, j)] + bs[j];
                sum += x; sq += x * x;
            }
            float mean = sum * (1.f / 128.f);
            float var  = sq * (1.f / 128.f) - mean * mean;
            ((float*)(smem + OFF_MEAN))[t] = mean;
            ((float*)(smem + OFF_RSTD))[t] = rsqrtf(var + 1e-5f);
        }
        __syncthreads();
    }

    if (MODE == 2) {
#pragma unroll
        for (int rep = 0; rep < 4; ++rep) {
            int i = t + rep * 512;
            int row = i >> 5, q = i & 31;
            int grow = tile0 + row;
            if (grow >= nrows) continue;
            int base = row * 128 + ((q ^ (row & 7)) << 2);
            float4 o;
            o.x = Csm[base + 0] + bs[q * 4 + 0];
            o.y = Csm[base + 1] + bs[q * 4 + 1];
            o.z = Csm[base + 2] + bs[q * 4 + 2];
            o.w = Csm[base + 3] + bs[q * 4 + 3];
            *reinterpret_cast<float4*>(outf + (size_t)grow * HH + q * 4) = o;
        }
    } else {
        const float* gg = (const float*)(smem + OFF_G);
        const float* bb = (const float*)(smem + OFF_BETA);
        const float* mn = (const float*)(smem + OFF_MEAN);
        const float* rs = (const float*)(smem + OFF_RSTD);
        // MODE1: x_hi at OFF_AH, x_lo at OFF_AL (natural, no swap)
        const uint32_t* rxh = (const uint32_t*)(smem + OFF_AH);
        const uint32_t* rxl = (const uint32_t*)(smem + OFF_AL);
#pragma unroll
        for (int rep = 0; rep < 8; ++rep) {
            int i = t + rep * 512;
            int row = i >> 6, cp = i & 63;
            int grow = tile0 + row;
            if (grow >= nrows) continue;
            int c0 = cp * 2;
            float x0 = Csm[CIDX(row, c0)]     + bs[c0];
            float x1 = Csm[CIDX(row, c0 + 1)] + bs[c0 + 1];
            float o0, o1;
            if (MODE == 1) {
                float mean = mn[row], rstd = rs[row];
                int idx = PIDX(row, cp);
                float2 rh = bf2f(rxh[idx]);
                float2 rl = bf2f(rxl[idx]);
                o0 = fmaxf((x0 - mean) * rstd * gg[c0]     + bb[c0],     0.f) + (rh.x + rl.x);
                o1 = fmaxf((x1 - mean) * rstd * gg[c0 + 1] + bb[c0 + 1], 0.f) + (rh.y + rl.y);
            } else {
                o0 = fmaxf(x0, 0.f);
                o1 = fmaxf(x1, 0.f);
            }
            uint32_t h0, l0, h1, l1;
            hilo(o0, h0, l0); hilo(o1, h1, l1);
            out[(size_t)grow * 128 + cp]      = h0 | (h1 << 16);
            out[(size_t)grow * 128 + 64 + cp] = l0 | (l1 << 16);
        }
    }
}

// ---------------- neighbor mean aggregation (hi plane only) ----------------
__global__ void __launch_bounds__(256) k_aggr(const uint32_t* __restrict__ x) {
    int warp = (blockIdx.x * blockDim.x + threadIdx.x) >> 5;
    int lane = threadIdx.x & 31;
    if (warp >= NN) return;
    int s0 = g_off[warp], s1 = g_off[warp + 1];
    float a0 = 0.f, a1 = 0.f, a2 = 0.f, a3 = 0.f;
    const uint2* xp = reinterpret_cast<const uint2*>(x);
#pragma unroll 4
    for (int i = s0; i < s1; ++i) {
        int nb = __ldg(&g_col[i]);
        uint2 v = __ldg(xp + (size_t)nb * 64 + lane);
        float2 f0 = bf2f(v.x), f1 = bf2f(v.y);
        a0 += f0.x; a1 += f0.y; a2 += f1.x; a3 += f1.y;
    }
    float inv = 1.f / fmaxf((float)(s1 - s0), 1.f);
    a0 *= inv; a1 *= inv; a2 *= inv; a3 *= inv;
    uint2 o;
    o.x = bfh(a0) | (bfh(a1) << 16);
    o.y = bfh(a2) | (bfh(a3) << 16);
    reinterpret_cast<uint2*>(g_agg)[(size_t)warp * 32 + lane] = o;
}

// ---------------- split softmax pool: partials ----------------
__global__ void __launch_bounds__(128) k_pool_part() {
    int b = blockIdx.x >> 3, p = blockIdx.x & 7;
    int s0 = g_gstart[b], s1 = g_gstart[b + 1];
    int len = s1 - s0;
    int q0 = s0 + (len * p) / SPLITS;
    int q1 = s0 + (len * (p + 1)) / SPLITS;
    int t = threadIdx.x;
    __shared__ float4 red[128];
    __shared__ float smax[4];

    float4 mx = make_float4(-1e30f, -1e30f, -1e30f, -1e30f);
    for (int n = q0 + t; n < q1; n += 128) {
        float4 f = reinterpret_cast<const float4*>(g_scores)[n];
        mx.x = fmaxf(mx.x, f.x); mx.y = fmaxf(mx.y, f.y);
        mx.z = fmaxf(mx.z, f.z); mx.w = fmaxf(mx.w, f.w);
    }
    red[t] = mx;
    __syncthreads();
    for (int s = 64; s > 0; s >>= 1) {
        if (t < s) {
            float4 a = red[t], c = red[t + s];
            a.x = fmaxf(a.x, c.x); a.y = fmaxf(a.y, c.y);
            a.z = fmaxf(a.z, c.z); a.w = fmaxf(a.w, c.w);
            red[t] = a;
        }
        __syncthreads();
    }
    if (t == 0) { smax[0] = red[0].x; smax[1] = red[0].y; smax[2] = red[0].z; smax[3] = red[0].w; }
    __syncthreads();

    int h = t >> 5;
    float m = smax[h];
    float pl = 0.f, den = 0.f;
#pragma unroll 2
    for (int n = q0; n < q1; ++n) {
        float e = expf(g_scores[n * 4 + h] - m);
        pl = fmaf(e, g_v[(size_t)n * HH + t], pl);
        den += e;
    }
    int slot = b * SPLITS + p;
    g_pp[slot * 128 + t] = pl;
    if ((t & 31) == 0) g_pd[slot * 4 + h] = den;
    if (t < 4) g_pm[slot * 4 + t] = smax[t];
}

// ---------------- tail (merges pool partials, then MLP heads) ----------------
__global__ void __launch_bounds__(128) k_tail(
    const float* __restrict__ out_W, const float* __restrict__ out_b,
    const float* __restrict__ symfeat,
    const float* __restrict__ sym_W, const float* __restrict__ sym_b,
    const float* __restrict__ symf_W, const float* __restrict__ symf_b,
    const float* __restrict__ symf_g, const float* __restrict__ symf_beta,
    const float* __restrict__ fus_W, const float* __restrict__ fus_b,
    const float* __restrict__ fus_g, const float* __restrict__ fus_beta,
    const float* __restrict__ hW1, const float* __restrict__ hb1,
    const float* __restrict__ hW2, const float* __restrict__ hb2,
    float* __restrict__ outp)
{
    int b = blockIdx.x;
    int t = threadIdx.x;
    __shared__ float M[4], Dn[4];
    __shared__ float p[128];
    __shared__ float cat[256];
    __shared__ float buf[128];
    __shared__ float hh[192];
    __shared__ float ws[4], wq[4];

    if (t < 4) {
        float mm = -1e30f;
        for (int pp = 0; pp < SPLITS; ++pp)
            mm = fmaxf(mm, g_pm[(b * SPLITS + pp) * 4 + t]);
        M[t] = mm;
        float d = 0.f;
        for (int pp = 0; pp < SPLITS; ++pp) {
            float m = g_pm[(b * SPLITS + pp) * 4 + t];
            d += g_pd[(b * SPLITS + pp) * 4 + t] * expf(m - mm);
        }
        Dn[t] = d;
    }
    __syncthreads();
    {
        int h = t >> 5;
        float acc = 0.f;
        for (int pp = 0; pp < SPLITS; ++pp) {
            float m = g_pm[(b * SPLITS + pp) * 4 + h];
            acc += g_pp[(b * SPLITS + pp) * 128 + t] * expf(m - M[h]);
        }
        p[t] = (Dn[h] > 0.f) ? acc / Dn[h] : 0.f;
    }
    __syncthreads();
    {
        float acc = out_b[t];
        for (int k = 0; k < 128; ++k) acc = fmaf(out_W[t * 128 + k], p[k], acc);
        cat[t] = acc;
    }
    {
        int f = t >> 5, o = t & 31;
        const float* sf = symfeat + b * 64 + f * 16;
        const float* w  = sym_W + (f * 32 + o) * 16;
        float s = sym_b[f * 32 + o];
#pragma unroll
        for (int i = 0; i < 16; ++i) s = fmaf(w[i], sf[i], s);
        buf[t] = fmaxf(s, 0.f);
    }
    __syncthreads();
    {
        float s2 = symf_b[t];
        for (int k = 0; k < 128; ++k) s2 = fmaf(symf_W[t * 128 + k], buf[k], s2);
        s2 = fmaxf(s2, 0.f);
        float ssum = warp_sum(s2);
        float sq = warp_sum(s2 * s2);
        int wd = t >> 5, ln = t & 31;
        if (ln == 0) { ws[wd] = ssum; wq[wd] = sq; }
        __syncthreads();
        float ts = ws[0] + ws[1] + ws[2] + ws[3];
        float tq = wq[0] + wq[1] + wq[2] + wq[3];
        __syncthreads();
        float mean = ts * (1.f / 128.f);
        float var  = tq * (1.f / 128.f) - mean * mean;
        cat[128 + t] = (s2 - mean) * rsqrtf(var + 1e-5f) * symf_g[t] + symf_beta[t];
    }
    __syncthreads();
    {
        float f = fus_b[t];
        for (int k = 0; k < 256; ++k) f = fmaf(fus_W[t * 256 + k], cat[k], f);
        f = fmaxf(f, 0.f);
        float ssum = warp_sum(f);
        float sq = warp_sum(f * f);
        int wd = t >> 5, ln = t & 31;
        if (ln == 0) { ws[wd] = ssum; wq[wd] = sq; }
        __syncthreads();
        float ts = ws[0] + ws[1] + ws[2] + ws[3];
        float tq = wq[0] + wq[1] + wq[2] + wq[3];
        __syncthreads();
        float mean = ts * (1.f / 128.f);
        float var  = tq * (1.f / 128.f) - mean * mean;
        p[t] = (f - mean) * rsqrtf(var + 1e-5f) * fus_g[t] + fus_beta[t];
    }
    __syncthreads();
    for (int idx = t; idx < 192; idx += 128) {
        int k = idx >> 6, o = idx & 63;
        const float* w = hW1 + (size_t)(k * 64 + o) * 128;
        float acc = hb1[k * 64 + o];
        for (int j = 0; j < 128; ++j) acc = fmaf(w[j], p[j], acc);
        hh[idx] = fmaxf(acc, 0.f);
    }
    __syncthreads();
    if (t < 3) {
        float z = hb2[t];
        for (int o = 0; o < 64; ++o) z = fmaf(hW2[t * 64 + o], hh[t * 64 + o], z);
        outp[t * BB + b] = 1.f / (1.f + expf(-z));
    }
}

// ---------------- host ----------------
extern "C" void kernel_launch(void* const* d_in, const int* in_sizes, int n_in,
                              void* d_out, int out_size) {
    const float* nf = nullptr;
    const float* symf = nullptr;
    const int* ei = nullptr;
    const int* batch = nullptr;
    const float* P[26];
    int pi = 0;
    for (int i = 0; i < n_in; ++i) {
        int sz = in_sizes[i];
        if (sz == NN * HH)       nf    = (const float*)d_in[i];
        else if (sz == BB * 64)  symf  = (const float*)d_in[i];
        else if (sz == 2 * EE)   ei    = (const int*)d_in[i];
        else if (sz == NN)       batch = (const int*)d_in[i];
        else if (pi < 26)        P[pi++] = (const float*)d_in[i];
    }
    const float *W_in = P[0], *b_in = P[1], *sage_Wl = P[2], *sage_bl = P[3],
                *sage_Wr = P[4], *ln_g = P[5], *ln_b = P[6], *query = P[7],
                *in_proj_W = P[8], *in_proj_b = P[9], *out_W = P[10], *out_b = P[11],
                *sym_W = P[12], *sym_b = P[13], *symf_W = P[14], *symf_b = P[15],
                *symf_g = P[16], *symf_beta = P[17], *fus_W = P[18], *fus_b = P[19],
                *fus_g = P[20], *fus_beta = P[21], *hW1 = P[22], *hb1 = P[23],
                *hW2 = P[24], *hb2 = P[25];

    uint32_t *pxA, *pxB, *pag;
    float* pv;
    cudaGetSymbolAddress((void**)&pxA, g_xA);
    cudaGetSymbolAddress((void**)&pxB, g_xB);
    cudaGetSymbolAddress((void**)&pag, g_agg);
    cudaGetSymbolAddress((void**)&pv,  g_v);

    cudaFuncSetAttribute((const void*)k_mma<0>, cudaFuncAttributeMaxDynamicSharedMemorySize, SMEM_BYTES);
    cudaFuncSetAttribute((const void*)k_mma<1>, cudaFuncAttributeMaxDynamicSharedMemorySize, SMEM_BYTES);
    cudaFuncSetAttribute((const void*)k_mma<2>, cudaFuncAttributeMaxDynamicSharedMemorySize, SMEM_BYTES);

    // serial single-stream chain (fork/merge concurrency measured as regressions in R12/R13)
    // weight slots: 0=W_in, 1=Wl0, 2=Wr0, 3=Wl1, 4=Wr1, 5=Wl2, 6=Wr2, 7=Wv
    k_setup1<<<324, 256>>>(W_in,
                           sage_Wl + 0 * 16384, sage_Wr + 0 * 16384,
                           sage_Wl + 1 * 16384, sage_Wr + 1 * 16384,
                           sage_Wl + 2 * 16384, sage_Wr + 2 * 16384,
                           in_proj_W + 256 * 128);
    k_deg<<<(EE + 1023) / 1024, 256>>>(ei);
    k_setup2<<<2 + (NN + 1023) / 1024, 1024>>>(in_proj_W, in_proj_b, query, batch);
    // index 3: input-proj GEMM (profiled sample slot)
    k_mma<0><<<TILES64, 512, SMEM_BYTES>>>(nf, nullptr, nullptr, 0, b_in,
                                           nullptr, nullptr, pxA, nullptr, NN);
    k_fill<<<(EE + 1023) / 1024, 256>>>(ei);

    uint32_t *cur = pxA, *nxt = pxB;
    for (int l = 0; l < 3; ++l) {
        k_aggr<<<(NN * 32 + 255) / 256, 256>>>(cur);
        k_mma<1><<<TILES64, 512, SMEM_BYTES>>>(nullptr, pag, cur, 1 + 2 * l,
                                               sage_bl + l * 128,
                                               ln_g + l * 128, ln_b + l * 128,
                                               nxt, nullptr, NN);
        uint32_t* tmp = cur; cur = nxt; nxt = tmp;
    }

    // v = x @ Wv^T + bv (fp32) + fused attention scores
    k_mma<2><<<TILES64, 512, SMEM_BYTES>>>(nullptr, cur, nullptr, 7, in_proj_b + 256,
                                           nullptr, nullptr, nullptr, pv, NN);

    k_pool_part<<<BB * SPLITS, 128>>>();
    k_tail<<<BB, 128>>>(out_W, out_b, symf, sym_W, sym_b,
                        symf_W, symf_b, symf_g, symf_beta,
                        fus_W, fus_b, fus_g, fus_beta,
                        hW1, hb1, hW2, hb2, (float*)d_out);
    (void)out_size;
}

// round 16
// speedup vs baseline: 1.0769x; 1.0769x over previous
#include <cuda_runtime.h>
#include <cuda_bf16.h>
#include <math.h>
#include <stdint.h>

#define NN 50000
#define EE 800000
#define BB 64
#define HH 128
#define TILES64 782   // ceil(50000/64)
#define SPLITS 8

// ---------------- scratch (device globals) ----------------
// x as interleaved bf16 hi/lo: per node 128 uint32 = [64 hi words | 64 lo words]
__device__ uint32_t g_xA [NN * 128];
__device__ uint32_t g_xB [NN * 128];
__device__ uint32_t g_agg[NN * 64];   // single bf16 plane (hi only)
__device__ float g_v   [NN * HH];
__device__ float g_scores[NN * 4];
__device__ float g_U[HH * 4];
__device__ float g_cvec[4];
__device__ float g_pm[BB * SPLITS * 4];
__device__ float g_pd[BB * SPLITS * 4];
__device__ float g_pp[BB * SPLITS * 128];
__device__ int   g_deg[NN];
__device__ int   g_off[NN + 1];
__device__ int   g_cur[NN];
__device__ int   g_col[EE];
__device__ int   g_gstart[BB + 1];
__device__ uint4 g_wbuf[8 * 4096];

// ---------------- helpers ----------------
__device__ __forceinline__ void hilo(float v, uint32_t& h, uint32_t& l) {
    __nv_bfloat16 hb = __float2bfloat16(v);
    __nv_bfloat16 lb = __float2bfloat16(v - __bfloat162float(hb));
    h = (uint32_t)__bfloat16_as_ushort(hb);
    l = (uint32_t)__bfloat16_as_ushort(lb);
}
__device__ __forceinline__ uint32_t bfh(float v) {
    return (uint32_t)__bfloat16_as_ushort(__float2bfloat16(v));
}
__device__ __forceinline__ float2 bf2f(uint32_t u) {
    __nv_bfloat162 h;
    *reinterpret_cast<uint32_t*>(&h) = u;
    return __bfloat1622float2(h);
}
__device__ __forceinline__ uint32_t smem_u32(const void* p) {
    uint32_t a;
    asm("{ .reg .u64 t; cvta.to.shared.u64 t, %1; cvt.u32.u64 %0, t; }" : "=r"(a) : "l"(p));
    return a;
}
__device__ __forceinline__ float warp_sum(float v) {
#pragma unroll
    for (int o = 16; o > 0; o >>= 1) v += __shfl_xor_sync(0xffffffffu, v, o);
    return v;
}

#define HMMA(C, A0, A1, A2, A3, B0, B1) \
    asm volatile("mma.sync.aligned.m16n8k16.row.col.f32.bf16.bf16.f32 " \
                 "{%0,%1,%2,%3}, {%4,%5,%6,%7}, {%8,%9}, {%0,%1,%2,%3};" \
                 : "+f"((C)[0]), "+f"((C)[1]), "+f"((C)[2]), "+f"((C)[3]) \
                 : "r"(A0), "r"(A1), "r"(A2), "r"(A3), "r"(B0), "r"(B1))

#define LDSM4(D0, D1, D2, D3, A) \
    asm volatile("ldmatrix.sync.aligned.m8n8.x4.shared.b16 {%0,%1,%2,%3}, [%4];" \
                 : "=r"(D0), "=r"(D1), "=r"(D2), "=r"(D3) : "r"(A))

#define CP_ASYNC16(dst, src, sz) \
    asm volatile("cp.async.cg.shared.global [%0], [%1], 16, %2;" \
                 :: "r"(dst), "l"(src), "r"(sz) : "memory")
#define CP_COMMIT() asm volatile("cp.async.commit_group;" ::: "memory")
#define CP_WAIT0()  asm volatile("cp.async.wait_group 0;" ::: "memory")

// ---------------- SMEM layout (64-row tile) ----------------
#define OFF_AH  0
#define OFF_AL  16384
#define OFF_WH  32768
#define OFF_WL  65536
#define OFF_MISC 98304
#define OFF_BIAS (OFF_MISC)
#define OFF_G    (OFF_MISC + 512)
#define OFF_BETA (OFF_MISC + 1024)
#define OFF_MEAN (OFF_MISC + 1536)
#define OFF_RSTD (OFF_MISC + 1856)
#define OFF_U    (OFF_MISC + 2176)
#define OFF_CV   (OFF_MISC + 4224)
#define SMEM_BYTES (OFF_MISC + 4256)

__device__ __forceinline__ int CIDX(int row, int col) {
    return row * 128 + (((col >> 2) ^ (row & 7)) << 2) + (col & 3);
}
__device__ __forceinline__ int PIDX(int row, int cp) {
    return row * 64 + (((cp >> 2) ^ (row & 7)) << 2) + (cp & 3);
}

// ---------------- setup1: CSR init + weight pre-conversion ----------------
__global__ void k_setup1(const float* w0, const float* w1, const float* w2, const float* w3,
                         const float* w4, const float* w5, const float* w6, const float* w7) {
    int b = blockIdx.x;
    if (b < 196) {
        int i = b * 256 + threadIdx.x;
        if (i < NN) { g_deg[i] = 0; g_cur[i] = 0; }
        return;
    }
    int bb = b - 196;
    int m = bb >> 4;
    const float* W;
    switch (m) {
        case 0: W = w0; break; case 1: W = w1; break; case 2: W = w2; break;
        case 3: W = w3; break; case 4: W = w4; break; case 5: W = w5; break;
        case 6: W = w6; break; default: W = w7; break;
    }
    int i = (bb & 15) * 256 + threadIdx.x;
    int row = i >> 5, q = i & 31;
    float4 v = *reinterpret_cast<const float4*>(W + (size_t)row * 128 + q * 4);
    uint32_t h0, l0, h1, l1, h2, l2, h3, l3;
    hilo(v.x, h0, l0); hilo(v.y, h1, l1); hilo(v.z, h2, l2); hilo(v.w, h3, l3);
    uint2 uh, ul;
    uh.x = h0 | (h1 << 16); uh.y = h2 | (h3 << 16);
    ul.x = l0 | (l1 << 16); ul.y = l2 | (l3 << 16);
    char* base = (char*)g_wbuf + (size_t)m * 65536;
    int sw = row * 256 + q * 8;
    *reinterpret_cast<uint2*>(base + sw)         = uh;
    *reinterpret_cast<uint2*>(base + 32768 + sw) = ul;
}

// ---------------- deg count ----------------
__global__ void k_deg(const int* __restrict__ ei) {
    int e = blockIdx.x * blockDim.x + threadIdx.x;
    if (e < EE) atomicAdd(&g_deg[ei[EE + e]], 1);
}

// ---------------- setup2: scan + attention prep + graph bounds ----------------
__global__ void __launch_bounds__(1024) k_setup2(const float* __restrict__ in_proj_W,
                                                 const float* __restrict__ in_proj_b,
                                                 const float* __restrict__ query,
                                                 const int* __restrict__ batch) {
    int t = threadIdx.x;
    if (blockIdx.x == 0) {
        __shared__ int sm[1024];
        const int chunk = (NN + 1023) / 1024;
        int base = t * chunk;
        int s = 0;
        for (int i = 0; i < chunk; ++i) {
            int idx = base + i;
            if (idx < NN) s += g_deg[idx];
        }
        sm[t] = s;
        __syncthreads();
        for (int d = 1; d < 1024; d <<= 1) {
            int add = (t >= d) ? sm[t - d] : 0;
            __syncthreads();
            sm[t] += add;
            __syncthreads();
        }
        int run = sm[t] - s;
        for (int i = 0; i < chunk; ++i) {
            int idx = base + i;
            if (idx < NN) { g_off[idx] = run; run += g_deg[idx]; }
        }
        if (t == 1023) g_off[NN] = sm[1023];
    } else if (blockIdx.x == 1) {
        __shared__ float qv[128];
        if (t < 128) {
            float s = in_proj_b[t];
            for (int k = 0; k < 128; ++k) s = fmaf(in_proj_W[t * 128 + k], query[k], s);
            qv[t] = s;
        }
        __syncthreads();
        if (t < 128) {
            const float inv = 1.0f / sqrtf(32.0f);
            float u[4] = {0.f, 0.f, 0.f, 0.f};
            for (int r = 0; r < 128; ++r) {
                float w = in_proj_W[(128 + r) * 128 + t];
                u[r >> 5] = fmaf(qv[r], w, u[r >> 5]);
            }
#pragma unroll
            for (int h = 0; h < 4; ++h) g_U[t * 4 + h] = u[h] * inv;
            if (t < 4) {
                float cc = 0.f;
                for (int d = 0; d < 32; ++d)
                    cc = fmaf(qv[t * 32 + d], in_proj_b[128 + t * 32 + d], cc);
                g_cvec[t] = cc * inv;
            }
        }
    } else {
        int i = (blockIdx.x - 2) * 1024 + t;
        if (i >= NN) return;
        int bi = batch[i];
        if (i == 0) {
            for (int g = 0; g <= bi; ++g) g_gstart[g] = 0;
        } else {
            int bp = batch[i - 1];
            for (int g = bp + 1; g <= bi; ++g) g_gstart[g] = i;
        }
        if (i == NN - 1) {
            for (int g = bi + 1; g <= BB; ++g) g_gstart[g] = NN;
        }
    }
}

// ---------------- CSR fill ----------------
__global__ void k_fill(const int* __restrict__ ei) {
    int e = blockIdx.x * blockDim.x + threadIdx.x;
    if (e < EE) {
        int s = ei[e];
        int d = ei[EE + e];
        int slot = atomicAdd(&g_cur[d], 1);
        g_col[g_off[d] + slot] = s;
    }
}

// ---------------- GEMM fills ----------------
__device__ __forceinline__ void fill_copy_async(const uint32_t* __restrict__ g,
                                                uint32_t sb, int tile0, int nrows, int t) {
#pragma unroll
    for (int rep = 0; rep < 4; ++rep) {
        int i = t + rep * 512;
        int row = i >> 5, c = i & 31;
        int grow = tile0 + row;
        int sz = (grow < nrows) ? 16 : 0;
        const char* src = (const char*)(g + (size_t)grow * 128) + c * 16;
        int cc = c & 15;
        int phys = row * 256 + ((cc ^ (row & 7)) << 4);
        uint32_t dst = sb + ((c < 16) ? OFF_AH : OFF_AL) + phys;
        CP_ASYNC16(dst, src, sz);
    }
}
__device__ __forceinline__ void fill_copy_hi(const uint32_t* __restrict__ g,
                                             uint32_t sb, uint32_t dstoff,
                                             int tile0, int nrows, int t) {
#pragma unroll
    for (int rep = 0; rep < 2; ++rep) {
        int i = t + rep * 512;
        int row = i >> 4, chunk = i & 15;
        int grow = tile0 + row;
        int sz = (grow < nrows) ? 16 : 0;
        const char* src = (const char*)(g + (size_t)grow * 128) + chunk * 16;
        int phys = row * 256 + ((chunk ^ (row & 7)) << 4);
        CP_ASYNC16(sb + dstoff + phys, src, sz);
    }
}
__device__ __forceinline__ void fill_copy_lo(const uint32_t* __restrict__ g,
                                             uint32_t sb, uint32_t dstoff,
                                             int tile0, int nrows, int t) {
#pragma unroll
    for (int rep = 0; rep < 2; ++rep) {
        int i = t + rep * 512;
        int row = i >> 4, chunk = i & 15;
        int grow = tile0 + row;
        int sz = (grow < nrows) ? 16 : 0;
        const char* src = (const char*)(g + (size_t)grow * 128) + (16 + chunk) * 16;
        int phys = row * 256 + ((chunk ^ (row & 7)) << 4);
        CP_ASYNC16(sb + dstoff + phys, src, sz);
    }
}
__device__ __forceinline__ void fill_copy_half(const uint32_t* __restrict__ g,
                                               uint32_t sb, int tile0, int nrows, int t) {
#pragma unroll
    for (int rep = 0; rep < 2; ++rep) {
        int i = t + rep * 512;
        int row = i >> 4, chunk = i & 15;
        int grow = tile0 + row;
        int sz = (grow < nrows) ? 16 : 0;
        const char* src = (const char*)(g + (size_t)grow * 64) + chunk * 16;
        int phys = row * 256 + ((chunk ^ (row & 7)) << 4);
        CP_ASYNC16(sb + OFF_AH + phys, src, sz);
    }
}
__device__ __forceinline__ void fill_W_async(int slot, uint32_t sb, int t) {
    const char* src = (const char*)g_wbuf + (size_t)slot * 65536;
#pragma unroll
    for (int rep = 0; rep < 4; ++rep) {
        int i = t + rep * 512;
        int row = i >> 4, chunk = i & 15;
        int phys = row * 256 + ((chunk ^ (row & 7)) << 4);
        CP_ASYNC16(sb + OFF_WH + phys, src + i * 16, 16);
        CP_ASYNC16(sb + OFF_WL + phys, src + 32768 + i * 16, 16);
    }
}
__device__ __forceinline__ void fill_Whi_async(int slot, uint32_t sb, uint32_t dstoff, int t) {
    const char* src = (const char*)g_wbuf + (size_t)slot * 65536;
#pragma unroll
    for (int rep = 0; rep < 4; ++rep) {
        int i = t + rep * 512;
        int row = i >> 4, chunk = i & 15;
        int phys = row * 256 + ((chunk ^ (row & 7)) << 4);
        CP_ASYNC16(sb + dstoff + phys, src + i * 16, 16);
    }
}
__device__ __forceinline__ void fill_convert(const float* __restrict__ A, char* smem,
                                             int tile0, int nrows, int t) {
    float4 v[4];
#pragma unroll
    for (int rep = 0; rep < 4; ++rep) {
        int i = t + rep * 512;
        int row = i >> 5, q = i & 31;
        int grow = tile0 + row;
        v[rep] = make_float4(0.f, 0.f, 0.f, 0.f);
        if (grow < nrows)
            v[rep] = __ldg(reinterpret_cast<const float4*>(A + (size_t)grow * HH + q * 4));
    }
#pragma unroll
    for (int rep = 0; rep < 4; ++rep) {
        int i = t + rep * 512;
        int row = i >> 5, q = i & 31;
        uint32_t h0, l0, h1, l1, h2, l2, h3, l3;
        hilo(v[rep].x, h0, l0); hilo(v[rep].y, h1, l1);
        hilo(v[rep].z, h2, l2); hilo(v[rep].w, h3, l3);
        uint2 uh, ul;
        uh.x = h0 | (h1 << 16); uh.y = h2 | (h3 << 16);
        ul.x = l0 | (l1 << 16); ul.y = l2 | (l3 << 16);
        int phys = row * 256 + (((q >> 1) ^ (row & 7)) << 4) + (q & 1) * 8;
        *reinterpret_cast<uint2*>(smem + OFF_AH + phys) = uh;
        *reinterpret_cast<uint2*>(smem + OFF_AL + phys) = ul;
    }
}

// ---------------- mainloop ----------------
// TERMS: 1 = Ah*Bh | 2 = Ah*Bh + Al*Bh | 3 = Ah*Bh + Ah*Bl + Al*Bh (B lo at boff+32768)
template <int TERMS>
__device__ __forceinline__ void mainloop(uint32_t sb, uint32_t aoff_hi, uint32_t aoff_lo,
                                         uint32_t boff, float c[4][4],
                                         int wm, int wn, int lane) {
    uint32_t rowA = wm * 16 + (lane & 15);
    uint32_t swA = rowA & 7;
    uint32_t aAddrH = sb + aoff_hi + rowA * 256;
    uint32_t aAddrL = sb + aoff_lo + rowA * 256;
    uint32_t halfA = lane >> 4;
    uint32_t wrow = sb + boff + (uint32_t)(wn * 32 + lane) * 256;
    uint32_t swB = lane & 7;
#pragma unroll
    for (int ks = 0; ks < 8; ++ks) {
        uint32_t bh0[4], bh1[4];
        uint32_t cb0 = (uint32_t)(((2 * ks) ^ swB) << 4);
        uint32_t cb1 = (uint32_t)(((2 * ks + 1) ^ swB) << 4);
        LDSM4(bh0[0], bh0[1], bh0[2], bh0[3], wrow + cb0);
        LDSM4(bh1[0], bh1[1], bh1[2], bh1[3], wrow + cb1);
        uint32_t bl0[4], bl1[4];
        if (TERMS == 3) {
            LDSM4(bl0[0], bl0[1], bl0[2], bl0[3], wrow + 32768 + cb0);
            LDSM4(bl1[0], bl1[1], bl1[2], bl1[3], wrow + 32768 + cb1);
        }
        uint32_t ca = (uint32_t)(((2 * ks + halfA) ^ swA) << 4);
        uint32_t ah0, ah1, ah2, ah3;
        LDSM4(ah0, ah1, ah2, ah3, aAddrH + ca);
        uint32_t al0, al1, al2, al3;
        if (TERMS >= 2) LDSM4(al0, al1, al2, al3, aAddrL + ca);
#pragma unroll
        for (int nb = 0; nb < 4; ++nb) {
            HMMA(c[nb], ah0, ah1, ah2, ah3, bh0[nb], bh1[nb]);
            if (TERMS == 3) HMMA(c[nb], ah0, ah1, ah2, ah3, bl0[nb], bl1[nb]);
            if (TERMS >= 2) HMMA(c[nb], al0, al1, al2, al3, bh0[nb], bh1[nb]);
        }
    }
}

// MODE: 0 = input proj (3-term, W hi/lo)
//       1 = SAGE: upfront {Wl_hi, Wr_hi, agg_hi->AH, x_hi->AL}; pass1 agg 1-term;
//                 mid-fill x_lo->AH; pass2 x 2-term (hi=AL, lo=AH); LN+relu+residual
//       2 = V proj + scores (2-term, Wv hi only)
template <int MODE>
__global__ void __launch_bounds__(512, 2) k_mma(
    const float* __restrict__ Afp,
    const uint32_t* __restrict__ p1, const uint32_t* __restrict__ p2,
    int wslot, const float* __restrict__ bias,
    const float* __restrict__ lng, const float* __restrict__ lnb,
    uint32_t* __restrict__ out, float* __restrict__ outf, int nrows)
{
    extern __shared__ char smem[];
    uint32_t sb = smem_u32(smem);
    int t = threadIdx.x, wid = t >> 5, lane = t & 31;
    int tile0 = blockIdx.x * 64;
    int wm = wid & 3, wn = wid >> 2;

    if (MODE == 0) {
        fill_W_async(wslot, sb, t);
    } else if (MODE == 1) {
        fill_Whi_async(wslot, sb, OFF_WH, t);
        fill_Whi_async(wslot + 1, sb, OFF_WL, t);
        fill_copy_half(p1, sb, tile0, nrows, t);
        fill_copy_hi(p2, sb, OFF_AL, tile0, nrows, t);
    } else {
        fill_Whi_async(wslot, sb, OFF_WH, t);
        fill_copy_async(p1, sb, tile0, nrows, t);
    }
    CP_COMMIT();

    if (t < 128) {
        ((float*)(smem + OFF_BIAS))[t] = bias[t];
        if (MODE == 1) {
            ((float*)(smem + OFF_G))[t]    = lng[t];
            ((float*)(smem + OFF_BETA))[t] = lnb[t];
        }
    }
    if (MODE == 2) {
        if (t >= 128 && t < 256) ((float4*)(smem + OFF_U))[t - 128] = ((const float4*)g_U)[t - 128];
        if (t == 256) *((float4*)(smem + OFF_CV)) = *((const float4*)g_cvec);
    }
    if (MODE == 0) fill_convert(Afp, smem, tile0, nrows, t);

    float c[4][4];
#pragma unroll
    for (int nb = 0; nb < 4; ++nb)
#pragma unroll
        for (int j = 0; j < 4; ++j) c[nb][j] = 0.f;

    CP_WAIT0();
    __syncthreads();

    if (MODE == 0)      mainloop<3>(sb, OFF_AH, OFF_AL, OFF_WH, c, wm, wn, lane);
    else if (MODE == 1) mainloop<1>(sb, OFF_AH, OFF_AH, OFF_WH, c, wm, wn, lane);
    else                mainloop<2>(sb, OFF_AH, OFF_AL, OFF_WH, c, wm, wn, lane);

    if (MODE == 1) {
        __syncthreads();
        fill_copy_lo(p2, sb, OFF_AH, tile0, nrows, t);
        CP_COMMIT();
        CP_WAIT0();
        __syncthreads();
        mainloop<2>(sb, OFF_AL, OFF_AH, OFF_WL, c, wm, wn, lane);
    }
    __syncthreads();

    if (MODE == 2) {
        if (t < 64) {
            int grow = tile0 + t;
            if (grow < nrows) {
                const uint32_t* ph = (const uint32_t*)(smem + OFF_AH);
                const uint32_t* pl = (const uint32_t*)(smem + OFF_AL);
                const float4* U4 = (const float4*)(smem + OFF_U);
                const float* cv = (const float*)(smem + OFF_CV);
                float a0 = cv[0], a1 = cv[1], a2 = cv[2], a3 = cv[3];
#pragma unroll
                for (int kk = 0; kk < 64; ++kk) {
                    int idx = PIDX(t, kk);
                    float2 h = bf2f(ph[idx]);
                    float2 l = bf2f(pl[idx]);
                    float x0 = h.x + l.x, x1 = h.y + l.y;
                    float4 u0 = U4[2 * kk];
                    float4 u1 = U4[2 * kk + 1];
                    a0 += x0 * u0.x + x1 * u1.x;
                    a1 += x0 * u0.y + x1 * u1.y;
                    a2 += x0 * u0.z + x1 * u1.z;
                    a3 += x0 * u0.w + x1 * u1.w;
                }
                float4 r; r.x = a0; r.y = a1; r.z = a2; r.w = a3;
                reinterpret_cast<float4*>(g_scores)[grow] = r;
            }
        }
        __syncthreads();
    }

    float* Csm = (float*)(smem + OFF_WH);
    int g = lane >> 2, tt = lane & 3;
    {
        int r0 = wm * 16 + g;
        int r1 = r0 + 8;
#pragma unroll
        for (int nb = 0; nb < 4; ++nb) {
            int col = wn * 32 + nb * 8 + tt * 2;
            Csm[CIDX(r0, col)]     = c[nb][0];
            Csm[CIDX(r0, col + 1)] = c[nb][1];
            Csm[CIDX(r1, col)]     = c[nb][2];
            Csm[CIDX(r1, col + 1)] = c[nb][3];
        }
    }
    __syncthreads();

    const float* bs = (const float*)(smem + OFF_BIAS);
    if (MODE == 1) {
        if (t < 64) {
            float sum = 0.f, sq = 0.f;
#pragma unroll
            for (int j = 0; j < 128; ++j) {
                float x = Csm[CIDX(t, j)] + bs[j];
                sum += x; sq += x * x;
            }
            float mean = sum * (1.f / 128.f);
            float var  = sq * (1.f / 128.f) - mean * mean;
            ((float*)(smem + OFF_MEAN))[t] = mean;
            ((float*)(smem + OFF_RSTD))[t] = rsqrtf(var + 1e-5f);
        }
        __syncthreads();
    }

    if (MODE == 2) {
#pragma unroll
        for (int rep = 0; rep < 4; ++rep) {
            int i = t + rep * 512;
            int row = i >> 5, q = i & 31;
            int grow = tile0 + row;
            if (grow >= nrows) continue;
            int base = row * 128 + ((q ^ (row & 7)) << 2);
            float4 o;
            o.x = Csm[base + 0] + bs[q * 4 + 0];
            o.y = Csm[base + 1] + bs[q * 4 + 1];
            o.z = Csm[base + 2] + bs[q * 4 + 2];
            o.w = Csm[base + 3] + bs[q * 4 + 3];
            *reinterpret_cast<float4*>(outf + (size_t)grow * HH + q * 4) = o;
        }
    } else {
        const float* gg = (const float*)(smem + OFF_G);
        const float* bb = (const float*)(smem + OFF_BETA);
        const float* mn = (const float*)(smem + OFF_MEAN);
        const float* rs = (const float*)(smem + OFF_RSTD);
        const uint32_t* rxh = (const uint32_t*)(smem + OFF_AL);
        const uint32_t* rxl = (const uint32_t*)(smem + OFF_AH);
#pragma unroll
        for (int rep = 0; rep < 8; ++rep) {
            int i = t + rep * 512;
            int row = i >> 6, cp = i & 63;
            int grow = tile0 + row;
            if (grow >= nrows) continue;
            int c0 = cp * 2;
            float x0 = Csm[CIDX(row, c0)]     + bs[c0];
            float x1 = Csm[CIDX(row, c0 + 1)] + bs[c0 + 1];
            float o0, o1;
            if (MODE == 1) {
                float mean = mn[row], rstd = rs[row];
                int idx = PIDX(row, cp);
                float2 rh = bf2f(rxh[idx]);
                float2 rl = bf2f(rxl[idx]);
                o0 = fmaxf((x0 - mean) * rstd * gg[c0]     + bb[c0],     0.f) + (rh.x + rl.x);
                o1 = fmaxf((x1 - mean) * rstd * gg[c0 + 1] + bb[c0 + 1], 0.f) + (rh.y + rl.y);
            } else {
                o0 = fmaxf(x0, 0.f);
                o1 = fmaxf(x1, 0.f);
            }
            uint32_t h0, l0, h1, l1;
            hilo(o0, h0, l0); hilo(o1, h1, l1);
            out[(size_t)grow * 128 + cp]      = h0 | (h1 << 16);
            out[(size_t)grow * 128 + 64 + cp] = l0 | (l1 << 16);
        }
    }
}

// ---------------- neighbor mean aggregation (hi plane only) ----------------
__global__ void __launch_bounds__(256) k_aggr(const uint32_t* __restrict__ x) {
    int warp = (blockIdx.x * blockDim.x + threadIdx.x) >> 5;
    int lane = threadIdx.x & 31;
    if (warp >= NN) return;
    int s0 = g_off[warp], s1 = g_off[warp + 1];
    float a0 = 0.f, a1 = 0.f, a2 = 0.f, a3 = 0.f;
    const uint2* xp = reinterpret_cast<const uint2*>(x);
#pragma unroll 4
    for (int i = s0; i < s1; ++i) {
        int nb = __ldg(&g_col[i]);
        uint2 v = __ldg(xp + (size_t)nb * 64 + lane);
        float2 f0 = bf2f(v.x), f1 = bf2f(v.y);
        a0 += f0.x; a1 += f0.y; a2 += f1.x; a3 += f1.y;
    }
    float inv = 1.f / fmaxf((float)(s1 - s0), 1.f);
    a0 *= inv; a1 *= inv; a2 *= inv; a3 *= inv;
    uint2 o;
    o.x = bfh(a0) | (bfh(a1) << 16);
    o.y = bfh(a2) | (bfh(a3) << 16);
    reinterpret_cast<uint2*>(g_agg)[(size_t)warp * 32 + lane] = o;
}

// ---------------- split softmax pool: partials ----------------
__global__ void __launch_bounds__(128) k_pool_part() {
    int b = blockIdx.x >> 3, p = blockIdx.x & 7;
    int s0 = g_gstart[b], s1 = g_gstart[b + 1];
    int len = s1 - s0;
    int q0 = s0 + (len * p) / SPLITS;
    int q1 = s0 + (len * (p + 1)) / SPLITS;
    int t = threadIdx.x;
    __shared__ float4 red[128];
    __shared__ float smax[4];

    float4 mx = make_float4(-1e30f, -1e30f, -1e30f, -1e30f);
    for (int n = q0 + t; n < q1; n += 128) {
        float4 f = reinterpret_cast<const float4*>(g_scores)[n];
        mx.x = fmaxf(mx.x, f.x); mx.y = fmaxf(mx.y, f.y);
        mx.z = fmaxf(mx.z, f.z); mx.w = fmaxf(mx.w, f.w);
    }
    red[t] = mx;
    __syncthreads();
    for (int s = 64; s > 0; s >>= 1) {
        if (t < s) {
            float4 a = red[t], c = red[t + s];
            a.x = fmaxf(a.x, c.x); a.y = fmaxf(a.y, c.y);
            a.z = fmaxf(a.z, c.z); a.w = fmaxf(a.w, c.w);
            red[t] = a;
        }
        __syncthreads();
    }
    if (t == 0) { smax[0] = red[0].x; smax[1] = red[0].y; smax[2] = red[0].z; smax[3] = red[0].w; }
    __syncthreads();

    int h = t >> 5;
    float m = smax[h];
    float pl = 0.f, den = 0.f;
#pragma unroll 2
    for (int n = q0; n < q1; ++n) {
        float e = expf(g_scores[n * 4 + h] - m);
        pl = fmaf(e, g_v[(size_t)n * HH + t], pl);
        den += e;
    }
    int slot = b * SPLITS + p;
    g_pp[slot * 128 + t] = pl;
    if ((t & 31) == 0) g_pd[slot * 4 + h] = den;
    if (t < 4) g_pm[slot * 4 + t] = smax[t];
}

// ---------------- tail (merges pool partials, then MLP heads) ----------------
__global__ void __launch_bounds__(128) k_tail(
    const float* __restrict__ out_W, const float* __restrict__ out_b,
    const float* __restrict__ symfeat,
    const float* __restrict__ sym_W, const float* __restrict__ sym_b,
    const float* __restrict__ symf_W, const float* __restrict__ symf_b,
    const float* __restrict__ symf_g, const float* __restrict__ symf_beta,
    const float* __restrict__ fus_W, const float* __restrict__ fus_b,
    const float* __restrict__ fus_g, const float* __restrict__ fus_beta,
    const float* __restrict__ hW1, const float* __restrict__ hb1,
    const float* __restrict__ hW2, const float* __restrict__ hb2,
    float* __restrict__ outp)
{
    int b = blockIdx.x;
    int t = threadIdx.x;
    __shared__ float M[4], Dn[4];
    __shared__ float p[128];
    __shared__ float cat[256];
    __shared__ float buf[128];
    __shared__ float hh[192];
    __shared__ float ws[4], wq[4];

    if (t < 4) {
        float mm = -1e30f;
        for (int pp = 0; pp < SPLITS; ++pp)
            mm = fmaxf(mm, g_pm[(b * SPLITS + pp) * 4 + t]);
        M[t] = mm;
        float d = 0.f;
        for (int pp = 0; pp < SPLITS; ++pp) {
            float m = g_pm[(b * SPLITS + pp) * 4 + t];
            d += g_pd[(b * SPLITS + pp) * 4 + t] * expf(m - mm);
        }
        Dn[t] = d;
    }
    __syncthreads();
    {
        int h = t >> 5;
        float acc = 0.f;
        for (int pp = 0; pp < SPLITS; ++pp) {
            float m = g_pm[(b * SPLITS + pp) * 4 + h];
            acc += g_pp[(b * SPLITS + pp) * 128 + t] * expf(m - M[h]);
        }
        p[t] = (Dn[h] > 0.f) ? acc / Dn[h] : 0.f;
    }
    __syncthreads();
    {
        float acc = out_b[t];
        for (int k = 0; k < 128; ++k) acc = fmaf(out_W[t * 128 + k], p[k], acc);
        cat[t] = acc;
    }
    {
        int f = t >> 5, o = t & 31;
        const float* sf = symfeat + b * 64 + f * 16;
        const float* w  = sym_W + (f * 32 + o) * 16;
        float s = sym_b[f * 32 + o];
#pragma unroll
        for (int i = 0; i < 16; ++i) s = fmaf(w[i], sf[i], s);
        buf[t] = fmaxf(s, 0.f);
    }
    __syncthreads();
    {
        float s2 = symf_b[t];
        for (int k = 0; k < 128; ++k) s2 = fmaf(symf_W[t * 128 + k], buf[k], s2);
        s2 = fmaxf(s2, 0.f);
        float ssum = warp_sum(s2);
        float sq = warp_sum(s2 * s2);
        int wd = t >> 5, ln = t & 31;
        if (ln == 0) { ws[wd] = ssum; wq[wd] = sq; }
        __syncthreads();
        float ts = ws[0] + ws[1] + ws[2] + ws[3];
        float tq = wq[0] + wq[1] + wq[2] + wq[3];
        __syncthreads();
        float mean = ts * (1.f / 128.f);
        float var  = tq * (1.f / 128.f) - mean * mean;
        cat[128 + t] = (s2 - mean) * rsqrtf(var + 1e-5f) * symf_g[t] + symf_beta[t];
    }
    __syncthreads();
    {
        float f = fus_b[t];
        for (int k = 0; k < 256; ++k) f = fmaf(fus_W[t * 256 + k], cat[k], f);
        f = fmaxf(f, 0.f);
        float ssum = warp_sum(f);
        float sq = warp_sum(f * f);
        int wd = t >> 5, ln = t & 31;
        if (ln == 0) { ws[wd] = ssum; wq[wd] = sq; }
        __syncthreads();
        float ts = ws[0] + ws[1] + ws[2] + ws[3];
        float tq = wq[0] + wq[1] + wq[2] + wq[3];
        __syncthreads();
        float mean = ts * (1.f / 128.f);
        float var  = tq * (1.f / 128.f) - mean * mean;
        p[t] = (f - mean) * rsqrtf(var + 1e-5f) * fus_g[t] + fus_beta[t];
    }
    __syncthreads();
    for (int idx = t; idx < 192; idx += 128) {
        int k = idx >> 6, o = idx & 63;
        const float* w = hW1 + (size_t)(k * 64 + o) * 128;
        float acc = hb1[k * 64 + o];
        for (int j = 0; j < 128; ++j) acc = fmaf(w[j], p[j], acc);
        hh[idx] = fmaxf(acc, 0.f);
    }
    __syncthreads();
    if (t < 3) {
        float z = hb2[t];
        for (int o = 0; o < 64; ++o) z = fmaf(hW2[t * 64 + o], hh[t * 64 + o], z);
        outp[t * BB + b] = 1.f / (1.f + expf(-z));
    }
}

// ---------------- host ----------------
extern "C" void kernel_launch(void* const* d_in, const int* in_sizes, int n_in,
                              void* d_out, int out_size) {
    const float* nf = nullptr;
    const float* symf = nullptr;
    const int* ei = nullptr;
    const int* batch = nullptr;
    const float* P[26];
    int pi = 0;
    for (int i = 0; i < n_in; ++i) {
        int sz = in_sizes[i];
        if (sz == NN * HH)       nf    = (const float*)d_in[i];
        else if (sz == BB * 64)  symf  = (const float*)d_in[i];
        else if (sz == 2 * EE)   ei    = (const int*)d_in[i];
        else if (sz == NN)       batch = (const int*)d_in[i];
        else if (pi < 26)        P[pi++] = (const float*)d_in[i];
    }
    const float *W_in = P[0], *b_in = P[1], *sage_Wl = P[2], *sage_bl = P[3],
                *sage_Wr = P[4], *ln_g = P[5], *ln_b = P[6], *query = P[7],
                *in_proj_W = P[8], *in_proj_b = P[9], *out_W = P[10], *out_b = P[11],
                *sym_W = P[12], *sym_b = P[13], *symf_W = P[14], *symf_b = P[15],
                *symf_g = P[16], *symf_beta = P[17], *fus_W = P[18], *fus_b = P[19],
                *fus_g = P[20], *fus_beta = P[21], *hW1 = P[22], *hb1 = P[23],
                *hW2 = P[24], *hb2 = P[25];

    uint32_t *pxA, *pxB, *pag;
    float* pv;
    cudaGetSymbolAddress((void**)&pxA, g_xA);
    cudaGetSymbolAddress((void**)&pxB, g_xB);
    cudaGetSymbolAddress((void**)&pag, g_agg);
    cudaGetSymbolAddress((void**)&pv,  g_v);

    cudaFuncSetAttribute((const void*)k_mma<0>, cudaFuncAttributeMaxDynamicSharedMemorySize, SMEM_BYTES);
    cudaFuncSetAttribute((const void*)k_mma<1>, cudaFuncAttributeMaxDynamicSharedMemorySize, SMEM_BYTES);
    cudaFuncSetAttribute((const void*)k_mma<2>, cudaFuncAttributeMaxDynamicSharedMemorySize, SMEM_BYTES);

    // serial single-stream chain — the measured-best R11 configuration
    // weight slots: 0=W_in, 1=Wl0, 2=Wr0, 3=Wl1, 4=Wr1, 5=Wl2, 6=Wr2, 7=Wv
    k_setup1<<<324, 256>>>(W_in,
                           sage_Wl + 0 * 16384, sage_Wr + 0 * 16384,
                           sage_Wl + 1 * 16384, sage_Wr + 1 * 16384,
                           sage_Wl + 2 * 16384, sage_Wr + 2 * 16384,
                           in_proj_W + 256 * 128);
    k_deg<<<(EE + 255) / 256, 256>>>(ei);
    k_setup2<<<2 + (NN + 1023) / 1024, 1024>>>(in_proj_W, in_proj_b, query, batch);
    // index 3: input-proj GEMM (profiled sample slot)
    k_mma<0><<<TILES64, 512, SMEM_BYTES>>>(nf, nullptr, nullptr, 0, b_in,
                                           nullptr, nullptr, pxA, nullptr, NN);
    k_fill<<<(EE + 255) / 256, 256>>>(ei);

    uint32_t *cur = pxA, *nxt = pxB;
    for (int l = 0; l < 3; ++l) {
        k_aggr<<<(NN * 32 + 255) / 256, 256>>>(cur);
        k_mma<1><<<TILES64, 512, SMEM_BYTES>>>(nullptr, pag, cur, 1 + 2 * l,
                                               sage_bl + l * 128,
                                               ln_g + l * 128, ln_b + l * 128,
                                               nxt, nullptr, NN);
        uint32_t* tmp = cur; cur = nxt; nxt = tmp;
    }

    // v = x @ Wv^T + bv (fp32) + fused attention scores
    k_mma<2><<<TILES64, 512, SMEM_BYTES>>>(nullptr, cur, nullptr, 7, in_proj_b + 256,
                                           nullptr, nullptr, nullptr, pv, NN);

    k_pool_part<<<BB * SPLITS, 128>>>();
    k_tail<<<BB, 128>>>(out_W, out_b, symf, sym_W, sym_b,
                        symf_W, symf_b, symf_g, symf_beta,
                        fus_W, fus_b, fus_g, fus_beta,
                        hW1, hb1, hW2, hb2, (float*)d_out);
    (void)out_size;
}

// round 17
// speedup vs baseline: 1.1009x; 1.0223x over previous
#include <cuda_runtime.h>
#include <cuda_bf16.h>
#include <math.h>
#include <stdint.h>

#define NN 50000
#define EE 800000
#define BB 64
#define HH 128
#define TILES64 782   // ceil(50000/64)
#define SPLITS 8

// ---------------- scratch (device globals) ----------------
// x as interleaved bf16 hi/lo: per node 128 uint32 = [64 hi words | 64 lo words]
__device__ uint32_t g_xA [NN * 128];
__device__ uint32_t g_xB [NN * 128];
__device__ uint32_t g_agg[NN * 64];   // single bf16 plane (hi only)
__device__ float g_v   [NN * HH];
__device__ float g_scores[NN * 4];
__device__ float g_U[HH * 4];
__device__ float g_cvec[4];
__device__ float g_pm[BB * SPLITS * 4];
__device__ float g_pd[BB * SPLITS * 4];
__device__ float g_pp[BB * SPLITS * 128];
__device__ int   g_deg[NN];
__device__ int   g_off[NN + 1];
__device__ int   g_cur[NN];
__device__ int   g_col[EE];
__device__ int   g_gstart[BB + 1];
__device__ uint4 g_wbuf[8 * 4096];

// ---------------- helpers ----------------
__device__ __forceinline__ void hilo(float v, uint32_t& h, uint32_t& l) {
    __nv_bfloat16 hb = __float2bfloat16(v);
    __nv_bfloat16 lb = __float2bfloat16(v - __bfloat162float(hb));
    h = (uint32_t)__bfloat16_as_ushort(hb);
    l = (uint32_t)__bfloat16_as_ushort(lb);
}
__device__ __forceinline__ uint32_t bfh(float v) {
    return (uint32_t)__bfloat16_as_ushort(__float2bfloat16(v));
}
__device__ __forceinline__ float2 bf2f(uint32_t u) {
    __nv_bfloat162 h;
    *reinterpret_cast<uint32_t*>(&h) = u;
    return __bfloat1622float2(h);
}
__device__ __forceinline__ uint32_t smem_u32(const void* p) {
    uint32_t a;
    asm("{ .reg .u64 t; cvta.to.shared.u64 t, %1; cvt.u32.u64 %0, t; }" : "=r"(a) : "l"(p));
    return a;
}
__device__ __forceinline__ float warp_sum(float v) {
#pragma unroll
    for (int o = 16; o > 0; o >>= 1) v += __shfl_xor_sync(0xffffffffu, v, o);
    return v;
}

#define HMMA(C, A0, A1, A2, A3, B0, B1) \
    asm volatile("mma.sync.aligned.m16n8k16.row.col.f32.bf16.bf16.f32 " \
                 "{%0,%1,%2,%3}, {%4,%5,%6,%7}, {%8,%9}, {%0,%1,%2,%3};" \
                 : "+f"((C)[0]), "+f"((C)[1]), "+f"((C)[2]), "+f"((C)[3]) \
                 : "r"(A0), "r"(A1), "r"(A2), "r"(A3), "r"(B0), "r"(B1))

#define LDSM4(D0, D1, D2, D3, A) \
    asm volatile("ldmatrix.sync.aligned.m8n8.x4.shared.b16 {%0,%1,%2,%3}, [%4];" \
                 : "=r"(D0), "=r"(D1), "=r"(D2), "=r"(D3) : "r"(A))

#define CP_ASYNC16(dst, src, sz) \
    asm volatile("cp.async.cg.shared.global [%0], [%1], 16, %2;" \
                 :: "r"(dst), "l"(src), "r"(sz) : "memory")
#define CP_COMMIT() asm volatile("cp.async.commit_group;" ::: "memory")
#define CP_WAIT0()  asm volatile("cp.async.wait_group 0;" ::: "memory")

// ---------------- SMEM layout (64-row tile) ----------------
#define OFF_AH  0
#define OFF_AL  16384
#define OFF_WH  32768
#define OFF_WL  65536
#define OFF_MISC 98304
#define OFF_BIAS (OFF_MISC)
#define OFF_G    (OFF_MISC + 512)
#define OFF_BETA (OFF_MISC + 1024)
#define OFF_MEAN (OFF_MISC + 1536)
#define OFF_RSTD (OFF_MISC + 1856)
#define OFF_U    (OFF_MISC + 2176)
#define OFF_CV   (OFF_MISC + 4224)
#define SMEM_BYTES (OFF_MISC + 4256)

__device__ __forceinline__ int CIDX(int row, int col) {
    return row * 128 + (((col >> 2) ^ (row & 7)) << 2) + (col & 3);
}
__device__ __forceinline__ int PIDX(int row, int cp) {
    return row * 64 + (((cp >> 2) ^ (row & 7)) << 2) + (cp & 3);
}

// ---------------- setup1: CSR init + weight pre-conversion ----------------
__global__ void k_setup1(const float* w0, const float* w1, const float* w2, const float* w3,
                         const float* w4, const float* w5, const float* w6, const float* w7) {
    int b = blockIdx.x;
    if (b < 196) {
        int i = b * 256 + threadIdx.x;
        if (i < NN) { g_deg[i] = 0; g_cur[i] = 0; }
        return;
    }
    int bb = b - 196;
    int m = bb >> 4;
    const float* W;
    switch (m) {
        case 0: W = w0; break; case 1: W = w1; break; case 2: W = w2; break;
        case 3: W = w3; break; case 4: W = w4; break; case 5: W = w5; break;
        case 6: W = w6; break; default: W = w7; break;
    }
    int i = (bb & 15) * 256 + threadIdx.x;
    int row = i >> 5, q = i & 31;
    float4 v = *reinterpret_cast<const float4*>(W + (size_t)row * 128 + q * 4);
    uint32_t h0, l0, h1, l1, h2, l2, h3, l3;
    hilo(v.x, h0, l0); hilo(v.y, h1, l1); hilo(v.z, h2, l2); hilo(v.w, h3, l3);
    uint2 uh, ul;
    uh.x = h0 | (h1 << 16); uh.y = h2 | (h3 << 16);
    ul.x = l0 | (l1 << 16); ul.y = l2 | (l3 << 16);
    char* base = (char*)g_wbuf + (size_t)m * 65536;
    int sw = row * 256 + q * 8;
    *reinterpret_cast<uint2*>(base + sw)         = uh;
    *reinterpret_cast<uint2*>(base + 32768 + sw) = ul;
}

// ---------------- deg count ----------------
__global__ void k_deg(const int* __restrict__ ei) {
    int e = blockIdx.x * blockDim.x + threadIdx.x;
    if (e < EE) atomicAdd(&g_deg[ei[EE + e]], 1);
}

// ---------------- setup2: scan + attention prep + graph bounds ----------------
__global__ void __launch_bounds__(1024) k_setup2(const float* __restrict__ in_proj_W,
                                                 const float* __restrict__ in_proj_b,
                                                 const float* __restrict__ query,
                                                 const int* __restrict__ batch) {
    int t = threadIdx.x;
    if (blockIdx.x == 0) {
        __shared__ int sm[1024];
        const int chunk = (NN + 1023) / 1024;
        int base = t * chunk;
        int s = 0;
        for (int i = 0; i < chunk; ++i) {
            int idx = base + i;
            if (idx < NN) s += g_deg[idx];
        }
        sm[t] = s;
        __syncthreads();
        for (int d = 1; d < 1024; d <<= 1) {
            int add = (t >= d) ? sm[t - d] : 0;
            __syncthreads();
            sm[t] += add;
            __syncthreads();
        }
        int run = sm[t] - s;
        for (int i = 0; i < chunk; ++i) {
            int idx = base + i;
            if (idx < NN) { g_off[idx] = run; run += g_deg[idx]; }
        }
        if (t == 1023) g_off[NN] = sm[1023];
    } else if (blockIdx.x == 1) {
        __shared__ float qv[128];
        if (t < 128) {
            float s = in_proj_b[t];
            for (int k = 0; k < 128; ++k) s = fmaf(in_proj_W[t * 128 + k], query[k], s);
            qv[t] = s;
        }
        __syncthreads();
        if (t < 128) {
            const float inv = 1.0f / sqrtf(32.0f);
            float u[4] = {0.f, 0.f, 0.f, 0.f};
            for (int r = 0; r < 128; ++r) {
                float w = in_proj_W[(128 + r) * 128 + t];
                u[r >> 5] = fmaf(qv[r], w, u[r >> 5]);
            }
#pragma unroll
            for (int h = 0; h < 4; ++h) g_U[t * 4 + h] = u[h] * inv;
            if (t < 4) {
                float cc = 0.f;
                for (int d = 0; d < 32; ++d)
                    cc = fmaf(qv[t * 32 + d], in_proj_b[128 + t * 32 + d], cc);
                g_cvec[t] = cc * inv;
            }
        }
    } else {
        int i = (blockIdx.x - 2) * 1024 + t;
        if (i >= NN) return;
        int bi = batch[i];
        if (i == 0) {
            for (int g = 0; g <= bi; ++g) g_gstart[g] = 0;
        } else {
            int bp = batch[i - 1];
            for (int g = bp + 1; g <= bi; ++g) g_gstart[g] = i;
        }
        if (i == NN - 1) {
            for (int g = bi + 1; g <= BB; ++g) g_gstart[g] = NN;
        }
    }
}

// ---------------- CSR fill ----------------
__global__ void k_fill(const int* __restrict__ ei) {
    int e = blockIdx.x * blockDim.x + threadIdx.x;
    if (e < EE) {
        int s = ei[e];
        int d = ei[EE + e];
        int slot = atomicAdd(&g_cur[d], 1);
        g_col[g_off[d] + slot] = s;
    }
}

// ---------------- GEMM fills ----------------
__device__ __forceinline__ void fill_copy_async(const uint32_t* __restrict__ g,
                                                uint32_t sb, int tile0, int nrows, int t) {
#pragma unroll
    for (int rep = 0; rep < 4; ++rep) {
        int i = t + rep * 512;
        int row = i >> 5, c = i & 31;
        int grow = tile0 + row;
        int sz = (grow < nrows) ? 16 : 0;
        const char* src = (const char*)(g + (size_t)grow * 128) + c * 16;
        int cc = c & 15;
        int phys = row * 256 + ((cc ^ (row & 7)) << 4);
        uint32_t dst = sb + ((c < 16) ? OFF_AH : OFF_AL) + phys;
        CP_ASYNC16(dst, src, sz);
    }
}
__device__ __forceinline__ void fill_copy_hi(const uint32_t* __restrict__ g,
                                             uint32_t sb, uint32_t dstoff,
                                             int tile0, int nrows, int t) {
#pragma unroll
    for (int rep = 0; rep < 2; ++rep) {
        int i = t + rep * 512;
        int row = i >> 4, chunk = i & 15;
        int grow = tile0 + row;
        int sz = (grow < nrows) ? 16 : 0;
        const char* src = (const char*)(g + (size_t)grow * 128) + chunk * 16;
        int phys = row * 256 + ((chunk ^ (row & 7)) << 4);
        CP_ASYNC16(sb + dstoff + phys, src, sz);
    }
}
__device__ __forceinline__ void fill_copy_lo(const uint32_t* __restrict__ g,
                                             uint32_t sb, uint32_t dstoff,
                                             int tile0, int nrows, int t) {
#pragma unroll
    for (int rep = 0; rep < 2; ++rep) {
        int i = t + rep * 512;
        int row = i >> 4, chunk = i & 15;
        int grow = tile0 + row;
        int sz = (grow < nrows) ? 16 : 0;
        const char* src = (const char*)(g + (size_t)grow * 128) + (16 + chunk) * 16;
        int phys = row * 256 + ((chunk ^ (row & 7)) << 4);
        CP_ASYNC16(sb + dstoff + phys, src, sz);
    }
}
__device__ __forceinline__ void fill_copy_half(const uint32_t* __restrict__ g,
                                               uint32_t sb, int tile0, int nrows, int t) {
#pragma unroll
    for (int rep = 0; rep < 2; ++rep) {
        int i = t + rep * 512;
        int row = i >> 4, chunk = i & 15;
        int grow = tile0 + row;
        int sz = (grow < nrows) ? 16 : 0;
        const char* src = (const char*)(g + (size_t)grow * 64) + chunk * 16;
        int phys = row * 256 + ((chunk ^ (row & 7)) << 4);
        CP_ASYNC16(sb + OFF_AH + phys, src, sz);
    }
}
__device__ __forceinline__ void fill_W_async(int slot, uint32_t sb, int t) {
    const char* src = (const char*)g_wbuf + (size_t)slot * 65536;
#pragma unroll
    for (int rep = 0; rep < 4; ++rep) {
        int i = t + rep * 512;
        int row = i >> 4, chunk = i & 15;
        int phys = row * 256 + ((chunk ^ (row & 7)) << 4);
        CP_ASYNC16(sb + OFF_WH + phys, src + i * 16, 16);
        CP_ASYNC16(sb + OFF_WL + phys, src + 32768 + i * 16, 16);
    }
}
__device__ __forceinline__ void fill_Whi_async(int slot, uint32_t sb, uint32_t dstoff, int t) {
    const char* src = (const char*)g_wbuf + (size_t)slot * 65536;
#pragma unroll
    for (int rep = 0; rep < 4; ++rep) {
        int i = t + rep * 512;
        int row = i >> 4, chunk = i & 15;
        int phys = row * 256 + ((chunk ^ (row & 7)) << 4);
        CP_ASYNC16(sb + dstoff + phys, src + i * 16, 16);
    }
}
__device__ __forceinline__ void fill_convert(const float* __restrict__ A, char* smem,
                                             int tile0, int nrows, int t) {
    float4 v[4];
#pragma unroll
    for (int rep = 0; rep < 4; ++rep) {
        int i = t + rep * 512;
        int row = i >> 5, q = i & 31;
        int grow = tile0 + row;
        v[rep] = make_float4(0.f, 0.f, 0.f, 0.f);
        if (grow < nrows)
            v[rep] = __ldg(reinterpret_cast<const float4*>(A + (size_t)grow * HH + q * 4));
    }
#pragma unroll
    for (int rep = 0; rep < 4; ++rep) {
        int i = t + rep * 512;
        int row = i >> 5, q = i & 31;
        uint32_t h0, l0, h1, l1, h2, l2, h3, l3;
        hilo(v[rep].x, h0, l0); hilo(v[rep].y, h1, l1);
        hilo(v[rep].z, h2, l2); hilo(v[rep].w, h3, l3);
        uint2 uh, ul;
        uh.x = h0 | (h1 << 16); uh.y = h2 | (h3 << 16);
        ul.x = l0 | (l1 << 16); ul.y = l2 | (l3 << 16);
        int phys = row * 256 + (((q >> 1) ^ (row & 7)) << 4) + (q & 1) * 8;
        *reinterpret_cast<uint2*>(smem + OFF_AH + phys) = uh;
        *reinterpret_cast<uint2*>(smem + OFF_AL + phys) = ul;
    }
}

// ---------------- mainloop ----------------
// TERMS: 1 = Ah*Bh | 2 = Ah*Bh + Al*Bh | 3 = Ah*Bh + Ah*Bl + Al*Bh (B lo at boff+32768)
template <int TERMS>
__device__ __forceinline__ void mainloop(uint32_t sb, uint32_t aoff_hi, uint32_t aoff_lo,
                                         uint32_t boff, float c[4][4],
                                         int wm, int wn, int lane) {
    uint32_t rowA = wm * 16 + (lane & 15);
    uint32_t swA = rowA & 7;
    uint32_t aAddrH = sb + aoff_hi + rowA * 256;
    uint32_t aAddrL = sb + aoff_lo + rowA * 256;
    uint32_t halfA = lane >> 4;
    uint32_t wrow = sb + boff + (uint32_t)(wn * 32 + lane) * 256;
    uint32_t swB = lane & 7;
#pragma unroll
    for (int ks = 0; ks < 8; ++ks) {
        uint32_t bh0[4], bh1[4];
        uint32_t cb0 = (uint32_t)(((2 * ks) ^ swB) << 4);
        uint32_t cb1 = (uint32_t)(((2 * ks + 1) ^ swB) << 4);
        LDSM4(bh0[0], bh0[1], bh0[2], bh0[3], wrow + cb0);
        LDSM4(bh1[0], bh1[1], bh1[2], bh1[3], wrow + cb1);
        uint32_t bl0[4], bl1[4];
        if (TERMS == 3) {
            LDSM4(bl0[0], bl0[1], bl0[2], bl0[3], wrow + 32768 + cb0);
            LDSM4(bl1[0], bl1[1], bl1[2], bl1[3], wrow + 32768 + cb1);
        }
        uint32_t ca = (uint32_t)(((2 * ks + halfA) ^ swA) << 4);
        uint32_t ah0, ah1, ah2, ah3;
        LDSM4(ah0, ah1, ah2, ah3, aAddrH + ca);
        uint32_t al0, al1, al2, al3;
        if (TERMS >= 2) LDSM4(al0, al1, al2, al3, aAddrL + ca);
#pragma unroll
        for (int nb = 0; nb < 4; ++nb) {
            HMMA(c[nb], ah0, ah1, ah2, ah3, bh0[nb], bh1[nb]);
            if (TERMS == 3) HMMA(c[nb], ah0, ah1, ah2, ah3, bl0[nb], bl1[nb]);
            if (TERMS >= 2) HMMA(c[nb], al0, al1, al2, al3, bh0[nb], bh1[nb]);
        }
    }
}

// MODE: 0 = input proj (3-term, W hi/lo)
//       1 = SAGE: upfront {Wl_hi, Wr_hi, agg_hi->AH, x_hi->AL}; pass1 agg 1-term;
//                 mid-fill x_lo->AH; pass2 x 2-term (hi=AL, lo=AH); LN+relu+residual
//       2 = V proj + scores (1-term leaf: x_hi only, Wv hi only)
template <int MODE>
__global__ void __launch_bounds__(512, 2) k_mma(
    const float* __restrict__ Afp,
    const uint32_t* __restrict__ p1, const uint32_t* __restrict__ p2,
    int wslot, const float* __restrict__ bias,
    const float* __restrict__ lng, const float* __restrict__ lnb,
    uint32_t* __restrict__ out, float* __restrict__ outf, int nrows)
{
    extern __shared__ char smem[];
    uint32_t sb = smem_u32(smem);
    int t = threadIdx.x, wid = t >> 5, lane = t & 31;
    int tile0 = blockIdx.x * 64;
    int wm = wid & 3, wn = wid >> 2;

    if (MODE == 0) {
        fill_W_async(wslot, sb, t);
    } else if (MODE == 1) {
        fill_Whi_async(wslot, sb, OFF_WH, t);
        fill_Whi_async(wslot + 1, sb, OFF_WL, t);
        fill_copy_half(p1, sb, tile0, nrows, t);
        fill_copy_hi(p2, sb, OFF_AL, tile0, nrows, t);
    } else {
        fill_Whi_async(wslot, sb, OFF_WH, t);
        fill_copy_hi(p1, sb, OFF_AH, tile0, nrows, t);  // x hi only (leaf GEMM)
    }
    CP_COMMIT();

    if (t < 128) {
        ((float*)(smem + OFF_BIAS))[t] = bias[t];
        if (MODE == 1) {
            ((float*)(smem + OFF_G))[t]    = lng[t];
            ((float*)(smem + OFF_BETA))[t] = lnb[t];
        }
    }
    if (MODE == 2) {
        if (t >= 128 && t < 256) ((float4*)(smem + OFF_U))[t - 128] = ((const float4*)g_U)[t - 128];
        if (t == 256) *((float4*)(smem + OFF_CV)) = *((const float4*)g_cvec);
    }
    if (MODE == 0) fill_convert(Afp, smem, tile0, nrows, t);

    float c[4][4];
#pragma unroll
    for (int nb = 0; nb < 4; ++nb)
#pragma unroll
        for (int j = 0; j < 4; ++j) c[nb][j] = 0.f;

    CP_WAIT0();
    __syncthreads();

    if (MODE == 0)      mainloop<3>(sb, OFF_AH, OFF_AL, OFF_WH, c, wm, wn, lane);
    else if (MODE == 1) mainloop<1>(sb, OFF_AH, OFF_AH, OFF_WH, c, wm, wn, lane);
    else                mainloop<1>(sb, OFF_AH, OFF_AH, OFF_WH, c, wm, wn, lane);

    if (MODE == 1) {
        __syncthreads();
        fill_copy_lo(p2, sb, OFF_AH, tile0, nrows, t);
        CP_COMMIT();
        CP_WAIT0();
        __syncthreads();
        mainloop<2>(sb, OFF_AL, OFF_AH, OFF_WL, c, wm, wn, lane);
    }
    __syncthreads();

    if (MODE == 2) {
        // fused attention scores from the x hi plane
        if (t < 64) {
            int grow = tile0 + t;
            if (grow < nrows) {
                const uint32_t* ph = (const uint32_t*)(smem + OFF_AH);
                const float4* U4 = (const float4*)(smem + OFF_U);
                const float* cv = (const float*)(smem + OFF_CV);
                float a0 = cv[0], a1 = cv[1], a2 = cv[2], a3 = cv[3];
#pragma unroll
                for (int kk = 0; kk < 64; ++kk) {
                    int idx = PIDX(t, kk);
                    float2 h = bf2f(ph[idx]);
                    float x0 = h.x, x1 = h.y;
                    float4 u0 = U4[2 * kk];
                    float4 u1 = U4[2 * kk + 1];
                    a0 += x0 * u0.x + x1 * u1.x;
                    a1 += x0 * u0.y + x1 * u1.y;
                    a2 += x0 * u0.z + x1 * u1.z;
                    a3 += x0 * u0.w + x1 * u1.w;
                }
                float4 r; r.x = a0; r.y = a1; r.z = a2; r.w = a3;
                reinterpret_cast<float4*>(g_scores)[grow] = r;
            }
        }
        __syncthreads();
    }

    float* Csm = (float*)(smem + OFF_WH);
    int g = lane >> 2, tt = lane & 3;
    {
        int r0 = wm * 16 + g;
        int r1 = r0 + 8;
#pragma unroll
        for (int nb = 0; nb < 4; ++nb) {
            int col = wn * 32 + nb * 8 + tt * 2;
            Csm[CIDX(r0, col)]     = c[nb][0];
            Csm[CIDX(r0, col + 1)] = c[nb][1];
            Csm[CIDX(r1, col)]     = c[nb][2];
            Csm[CIDX(r1, col + 1)] = c[nb][3];
        }
    }
    __syncthreads();

    const float* bs = (const float*)(smem + OFF_BIAS);
    if (MODE == 1) {
        if (t < 64) {
            float sum = 0.f, sq = 0.f;
#pragma unroll
            for (int j = 0; j < 128; ++j) {
                float x = Csm[CIDX(t, j)] + bs[j];
                sum += x; sq += x * x;
            }
            float mean = sum * (1.f / 128.f);
            float var  = sq * (1.f / 128.f) - mean * mean;
            ((float*)(smem + OFF_MEAN))[t] = mean;
            ((float*)(smem + OFF_RSTD))[t] = rsqrtf(var + 1e-5f);
        }
        __syncthreads();
    }

    if (MODE == 2) {
#pragma unroll
        for (int rep = 0; rep < 4; ++rep) {
            int i = t + rep * 512;
            int row = i >> 5, q = i & 31;
            int grow = tile0 + row;
            if (grow >= nrows) continue;
            int base = row * 128 + ((q ^ (row & 7)) << 2);
            float4 o;
            o.x = Csm[base + 0] + bs[q * 4 + 0];
            o.y = Csm[base + 1] + bs[q * 4 + 1];
            o.z = Csm[base + 2] + bs[q * 4 + 2];
            o.w = Csm[base + 3] + bs[q * 4 + 3];
            *reinterpret_cast<float4*>(outf + (size_t)grow * HH + q * 4) = o;
        }
    } else {
        const float* gg = (const float*)(smem + OFF_G);
        const float* bb = (const float*)(smem + OFF_BETA);
        const float* mn = (const float*)(smem + OFF_MEAN);
        const float* rs = (const float*)(smem + OFF_RSTD);
        const uint32_t* rxh = (const uint32_t*)(smem + OFF_AL);
        const uint32_t* rxl = (const uint32_t*)(smem + OFF_AH);
#pragma unroll
        for (int rep = 0; rep < 8; ++rep) {
            int i = t + rep * 512;
            int row = i >> 6, cp = i & 63;
            int grow = tile0 + row;
            if (grow >= nrows) continue;
            int c0 = cp * 2;
            float x0 = Csm[CIDX(row, c0)]     + bs[c0];
            float x1 = Csm[CIDX(row, c0 + 1)] + bs[c0 + 1];
            float o0, o1;
            if (MODE == 1) {
                float mean = mn[row], rstd = rs[row];
                int idx = PIDX(row, cp);
                float2 rh = bf2f(rxh[idx]);
                float2 rl = bf2f(rxl[idx]);
                o0 = fmaxf((x0 - mean) * rstd * gg[c0]     + bb[c0],     0.f) + (rh.x + rl.x);
                o1 = fmaxf((x1 - mean) * rstd * gg[c0 + 1] + bb[c0 + 1], 0.f) + (rh.y + rl.y);
            } else {
                o0 = fmaxf(x0, 0.f);
                o1 = fmaxf(x1, 0.f);
            }
            uint32_t h0, l0, h1, l1;
            hilo(o0, h0, l0); hilo(o1, h1, l1);
            out[(size_t)grow * 128 + cp]      = h0 | (h1 << 16);
            out[(size_t)grow * 128 + 64 + cp] = l0 | (l1 << 16);
        }
    }
}

// ---------------- neighbor mean aggregation (hi plane only) ----------------
__global__ void __launch_bounds__(256) k_aggr(const uint32_t* __restrict__ x) {
    int warp = (blockIdx.x * blockDim.x + threadIdx.x) >> 5;
    int lane = threadIdx.x & 31;
    if (warp >= NN) return;
    int s0 = g_off[warp], s1 = g_off[warp + 1];
    float a0 = 0.f, a1 = 0.f, a2 = 0.f, a3 = 0.f;
    const uint2* xp = reinterpret_cast<const uint2*>(x);
#pragma unroll 4
    for (int i = s0; i < s1; ++i) {
        int nb = __ldg(&g_col[i]);
        uint2 v = __ldg(xp + (size_t)nb * 64 + lane);
        float2 f0 = bf2f(v.x), f1 = bf2f(v.y);
        a0 += f0.x; a1 += f0.y; a2 += f1.x; a3 += f1.y;
    }
    float inv = 1.f / fmaxf((float)(s1 - s0), 1.f);
    a0 *= inv; a1 *= inv; a2 *= inv; a3 *= inv;
    uint2 o;
    o.x = bfh(a0) | (bfh(a1) << 16);
    o.y = bfh(a2) | (bfh(a3) << 16);
    reinterpret_cast<uint2*>(g_agg)[(size_t)warp * 32 + lane] = o;
}

// ---------------- split softmax pool: partials ----------------
__global__ void __launch_bounds__(128) k_pool_part() {
    int b = blockIdx.x >> 3, p = blockIdx.x & 7;
    int s0 = g_gstart[b], s1 = g_gstart[b + 1];
    int len = s1 - s0;
    int q0 = s0 + (len * p) / SPLITS;
    int q1 = s0 + (len * (p + 1)) / SPLITS;
    int t = threadIdx.x;
    __shared__ float4 red[128];
    __shared__ float smax[4];

    float4 mx = make_float4(-1e30f, -1e30f, -1e30f, -1e30f);
    for (int n = q0 + t; n < q1; n += 128) {
        float4 f = reinterpret_cast<const float4*>(g_scores)[n];
        mx.x = fmaxf(mx.x, f.x); mx.y = fmaxf(mx.y, f.y);
        mx.z = fmaxf(mx.z, f.z); mx.w = fmaxf(mx.w, f.w);
    }
    red[t] = mx;
    __syncthreads();
    for (int s = 64; s > 0; s >>= 1) {
        if (t < s) {
            float4 a = red[t], c = red[t + s];
            a.x = fmaxf(a.x, c.x); a.y = fmaxf(a.y, c.y);
            a.z = fmaxf(a.z, c.z); a.w = fmaxf(a.w, c.w);
            red[t] = a;
        }
        __syncthreads();
    }
    if (t == 0) { smax[0] = red[0].x; smax[1] = red[0].y; smax[2] = red[0].z; smax[3] = red[0].w; }
    __syncthreads();

    int h = t >> 5;
    float m = smax[h];
    float pl = 0.f, den = 0.f;
#pragma unroll 2
    for (int n = q0; n < q1; ++n) {
        float e = expf(g_scores[n * 4 + h] - m);
        pl = fmaf(e, g_v[(size_t)n * HH + t], pl);
        den += e;
    }
    int slot = b * SPLITS + p;
    g_pp[slot * 128 + t] = pl;
    if ((t & 31) == 0) g_pd[slot * 4 + h] = den;
    if (t < 4) g_pm[slot * 4 + t] = smax[t];
}

// ---------------- tail (merges pool partials, then MLP heads) ----------------
__global__ void __launch_bounds__(128) k_tail(
    const float* __restrict__ out_W, const float* __restrict__ out_b,
    const float* __restrict__ symfeat,
    const float* __restrict__ sym_W, const float* __restrict__ sym_b,
    const float* __restrict__ symf_W, const float* __restrict__ symf_b,
    const float* __restrict__ symf_g, const float* __restrict__ symf_beta,
    const float* __restrict__ fus_W, const float* __restrict__ fus_b,
    const float* __restrict__ fus_g, const float* __restrict__ fus_beta,
    const float* __restrict__ hW1, const float* __restrict__ hb1,
    const float* __restrict__ hW2, const float* __restrict__ hb2,
    float* __restrict__ outp)
{
    int b = blockIdx.x;
    int t = threadIdx.x;
    __shared__ float M[4], Dn[4];
    __shared__ float p[128];
    __shared__ float cat[256];
    __shared__ float buf[128];
    __shared__ float hh[192];
    __shared__ float ws[4], wq[4];

    if (t < 4) {
        float mm = -1e30f;
        for (int pp = 0; pp < SPLITS; ++pp)
            mm = fmaxf(mm, g_pm[(b * SPLITS + pp) * 4 + t]);
        M[t] = mm;
        float d = 0.f;
        for (int pp = 0; pp < SPLITS; ++pp) {
            float m = g_pm[(b * SPLITS + pp) * 4 + t];
            d += g_pd[(b * SPLITS + pp) * 4 + t] * expf(m - mm);
        }
        Dn[t] = d;
    }
    __syncthreads();
    {
        int h = t >> 5;
        float acc = 0.f;
        for (int pp = 0; pp < SPLITS; ++pp) {
            float m = g_pm[(b * SPLITS + pp) * 4 + h];
            acc += g_pp[(b * SPLITS + pp) * 128 + t] * expf(m - M[h]);
        }
        p[t] = (Dn[h] > 0.f) ? acc / Dn[h] : 0.f;
    }
    __syncthreads();
    {
        float acc = out_b[t];
        for (int k = 0; k < 128; ++k) acc = fmaf(out_W[t * 128 + k], p[k], acc);
        cat[t] = acc;
    }
    {
        int f = t >> 5, o = t & 31;
        const float* sf = symfeat + b * 64 + f * 16;
        const float* w  = sym_W + (f * 32 + o) * 16;
        float s = sym_b[f * 32 + o];
#pragma unroll
        for (int i = 0; i < 16; ++i) s = fmaf(w[i], sf[i], s);
        buf[t] = fmaxf(s, 0.f);
    }
    __syncthreads();
    {
        float s2 = symf_b[t];
        for (int k = 0; k < 128; ++k) s2 = fmaf(symf_W[t * 128 + k], buf[k], s2);
        s2 = fmaxf(s2, 0.f);
        float ssum = warp_sum(s2);
        float sq = warp_sum(s2 * s2);
        int wd = t >> 5, ln = t & 31;
        if (ln == 0) { ws[wd] = ssum; wq[wd] = sq; }
        __syncthreads();
        float ts = ws[0] + ws[1] + ws[2] + ws[3];
        float tq = wq[0] + wq[1] + wq[2] + wq[3];
        __syncthreads();
        float mean = ts * (1.f / 128.f);
        float var  = tq * (1.f / 128.f) - mean * mean;
        cat[128 + t] = (s2 - mean) * rsqrtf(var + 1e-5f) * symf_g[t] + symf_beta[t];
    }
    __syncthreads();
    {
        float f = fus_b[t];
        for (int k = 0; k < 256; ++k) f = fmaf(fus_W[t * 256 + k], cat[k], f);
        f = fmaxf(f, 0.f);
        float ssum = warp_sum(f);
        float sq = warp_sum(f * f);
        int wd = t >> 5, ln = t & 31;
        if (ln == 0) { ws[wd] = ssum; wq[wd] = sq; }
        __syncthreads();
        float ts = ws[0] + ws[1] + ws[2] + ws[3];
        float tq = wq[0] + wq[1] + wq[2] + wq[3];
        __syncthreads();
        float mean = ts * (1.f / 128.f);
        float var  = tq * (1.f / 128.f) - mean * mean;
        p[t] = (f - mean) * rsqrtf(var + 1e-5f) * fus_g[t] + fus_beta[t];
    }
    __syncthreads();
    for (int idx = t; idx < 192; idx += 128) {
        int k = idx >> 6, o = idx & 63;
        const float* w = hW1 + (size_t)(k * 64 + o) * 128;
        float acc = hb1[k * 64 + o];
        for (int j = 0; j < 128; ++j) acc = fmaf(w[j], p[j], acc);
        hh[idx] = fmaxf(acc, 0.f);
    }
    __syncthreads();
    if (t < 3) {
        float z = hb2[t];
        for (int o = 0; o < 64; ++o) z = fmaf(hW2[t * 64 + o], hh[t * 64 + o], z);
        outp[t * BB + b] = 1.f / (1.f + expf(-z));
    }
}

// ---------------- host ----------------
extern "C" void kernel_launch(void* const* d_in, const int* in_sizes, int n_in,
                              void* d_out, int out_size) {
    const float* nf = nullptr;
    const float* symf = nullptr;
    const int* ei = nullptr;
    const int* batch = nullptr;
    const float* P[26];
    int pi = 0;
    for (int i = 0; i < n_in; ++i) {
        int sz = in_sizes[i];
        if (sz == NN * HH)       nf    = (const float*)d_in[i];
        else if (sz == BB * 64)  symf  = (const float*)d_in[i];
        else if (sz == 2 * EE)   ei    = (const int*)d_in[i];
        else if (sz == NN)       batch = (const int*)d_in[i];
        else if (pi < 26)        P[pi++] = (const float*)d_in[i];
    }
    const float *W_in = P[0], *b_in = P[1], *sage_Wl = P[2], *sage_bl = P[3],
                *sage_Wr = P[4], *ln_g = P[5], *ln_b = P[6], *query = P[7],
                *in_proj_W = P[8], *in_proj_b = P[9], *out_W = P[10], *out_b = P[11],
                *sym_W = P[12], *sym_b = P[13], *symf_W = P[14], *symf_b = P[15],
                *symf_g = P[16], *symf_beta = P[17], *fus_W = P[18], *fus_b = P[19],
                *fus_g = P[20], *fus_beta = P[21], *hW1 = P[22], *hb1 = P[23],
                *hW2 = P[24], *hb2 = P[25];

    uint32_t *pxA, *pxB, *pag;
    float* pv;
    cudaGetSymbolAddress((void**)&pxA, g_xA);
    cudaGetSymbolAddress((void**)&pxB, g_xB);
    cudaGetSymbolAddress((void**)&pag, g_agg);
    cudaGetSymbolAddress((void**)&pv,  g_v);

    cudaFuncSetAttribute((const void*)k_mma<0>, cudaFuncAttributeMaxDynamicSharedMemorySize, SMEM_BYTES);
    cudaFuncSetAttribute((const void*)k_mma<1>, cudaFuncAttributeMaxDynamicSharedMemorySize, SMEM_BYTES);
    cudaFuncSetAttribute((const void*)k_mma<2>, cudaFuncAttributeMaxDynamicSharedMemorySize, SMEM_BYTES);

    // serial single-stream chain — R11 structure + 1-term leaf V-projection
    // weight slots: 0=W_in, 1=Wl0, 2=Wr0, 3=Wl1, 4=Wr1, 5=Wl2, 6=Wr2, 7=Wv
    k_setup1<<<324, 256>>>(W_in,
                           sage_Wl + 0 * 16384, sage_Wr + 0 * 16384,
                           sage_Wl + 1 * 16384, sage_Wr + 1 * 16384,
                           sage_Wl + 2 * 16384, sage_Wr + 2 * 16384,
                           in_proj_W + 256 * 128);
    k_deg<<<(EE + 255) / 256, 256>>>(ei);
    k_setup2<<<2 + (NN + 1023) / 1024, 1024>>>(in_proj_W, in_proj_b, query, batch);
    // index 3: input-proj GEMM (profiled sample slot)
    k_mma<0><<<TILES64, 512, SMEM_BYTES>>>(nf, nullptr, nullptr, 0, b_in,
                                           nullptr, nullptr, pxA, nullptr, NN);
    k_fill<<<(EE + 255) / 256, 256>>>(ei);

    uint32_t *cur = pxA, *nxt = pxB;
    for (int l = 0; l < 3; ++l) {
        k_aggr<<<(NN * 32 + 255) / 256, 256>>>(cur);
        k_mma<1><<<TILES64, 512, SMEM_BYTES>>>(nullptr, pag, cur, 1 + 2 * l,
                                               sage_bl + l * 128,
                                               ln_g + l * 128, ln_b + l * 128,
                                               nxt, nullptr, NN);
        uint32_t* tmp = cur; cur = nxt; nxt = tmp;
    }

    // v = x_hi @ Wv_hi^T + bv (fp32, 1-term leaf) + fused attention scores
    k_mma<2><<<TILES64, 512, SMEM_BYTES>>>(nullptr, cur, nullptr, 7, in_proj_b + 256,
                                           nullptr, nullptr, nullptr, pv, NN);

    k_pool_part<<<BB * SPLITS, 128>>>();
    k_tail<<<BB, 128>>>(out_W, out_b, symf, sym_W, sym_b,
                        symf_W, symf_b, symf_g, symf_beta,
                        fus_W, fus_b, fus_g, fus_beta,
                        hW1, hb1, hW2, hb2, (float*)d_out);
    (void)out_size;
}